// round 7
// baseline (speedup 1.0000x reference)
#include <cuda_runtime.h>
#include <cuda.h>
#include <cstdint>
#include <math.h>

// Problem constants
constexpr int BB = 2;       // batch
constexpr int CC = 512;     // channels
constexpr int NN = 4096;    // spatial (64*64)
constexpr int DD = 64;      // qk dim
constexpr int QK = 128;     // stacked q|k dim

// ---------------------------------------------------------------------------
// Scratch (static __device__ — no runtime allocation)
// ---------------------------------------------------------------------------
__device__ __align__(1024) float g_qk [(size_t)BB * NN * QK];   // [b][n][q|k]
__device__ __align__(1024) float g_v  [(size_t)BB * CC * NN];   // [b][c][j] tf32
__device__ __align__(1024) float g_xT [(size_t)BB * NN * CC];   // [b][n][c] tf32
__device__ __align__(1024) float g_wr [(size_t)CC * CC];        // Wv tf32
__device__ __align__(1024) float g_wqk[(size_t)QK * CC];        // Wq|Wk tf32
__device__ __align__(1024) float g_bqk[QK];                     // bq|bk

// ---------------------------------------------------------------------------
// PTX helpers
// ---------------------------------------------------------------------------
__device__ __forceinline__ uint32_t smem_to_u32(const void* p) {
    uint32_t a;
    asm("{ .reg .u64 t; cvta.to.shared.u64 t, %1; cvt.u32.u64 %0, t; }"
        : "=r"(a) : "l"(p));
    return a;
}
__device__ __forceinline__ float tf32r(float v) {
    uint32_t o;
    asm("cvt.rna.tf32.f32 %0, %1;" : "=r"(o) : "f"(v));
    return __uint_as_float(o);
}

#define MBARRIER_INIT(addr, cnt) \
    asm volatile("mbarrier.init.shared.b64 [%0], %1;" \
        :: "r"((uint32_t)(addr)), "r"((uint32_t)(cnt)) : "memory")
#define MBARRIER_EXPECT_TX(addr, bytes) \
    asm volatile("mbarrier.arrive.expect_tx.shared.b64 _, [%0], %1;" \
        :: "r"((uint32_t)(addr)), "r"((uint32_t)(bytes)) : "memory")
#define MBARRIER_ARRIVE(addr) \
    asm volatile("mbarrier.arrive.shared.b64 _, [%0];" \
        :: "r"((uint32_t)(addr)) : "memory")
#define MBARRIER_WAIT_PARITY(addr, parity) do { \
    uint32_t _m = (uint32_t)(addr); uint32_t _p = (uint32_t)(parity); uint32_t _d; \
    asm volatile("{\n\t.reg .pred p;\n\t" \
        "mbarrier.try_wait.parity.shared.b64 p, [%1], %2;\n\t" \
        "selp.b32 %0, 1, 0, p;\n\t}" : "=r"(_d) : "r"(_m), "r"(_p) : "memory"); \
    if (!_d) { \
        asm volatile("{\n\t.reg .pred P1;\n\tWL_%=:\n\t" \
            "mbarrier.try_wait.parity.shared.b64 P1, [%0], %1, 0x989680;\n\t" \
            "@P1 bra.uni WD_%=;\n\tbra.uni WL_%=;\n\tWD_%=:\n\t}" \
            :: "r"(_m), "r"(_p) : "memory"); \
    } } while (0)

#define TMA_LOAD_3D(smem_addr, tmap, cx, cy, cz, mbar) \
    asm volatile( \
        "cp.async.bulk.tensor.3d.shared::cta.global.tile.mbarrier::complete_tx::bytes " \
        "[%0], [%1, {%2, %3, %4}], [%5];" \
        :: "r"((uint32_t)(smem_addr)), "l"(tmap), \
           "r"((int32_t)(cx)), "r"((int32_t)(cy)), "r"((int32_t)(cz)), \
           "r"((uint32_t)(mbar)) : "memory")

#define LDSM_X4(r0, r1, r2, r3, addr) \
    asm volatile("ldmatrix.sync.aligned.m8n8.x4.shared.b16 {%0,%1,%2,%3}, [%4];" \
        : "=r"(r0), "=r"(r1), "=r"(r2), "=r"(r3) : "r"(addr))

__device__ __forceinline__ void mma_tf32(float* d, const uint32_t* a, const uint32_t* b) {
    asm volatile(
        "mma.sync.aligned.m16n8k8.row.col.f32.tf32.tf32.f32 "
        "{%0,%1,%2,%3}, {%4,%5,%6,%7}, {%8,%9}, {%0,%1,%2,%3};"
        : "+f"(d[0]), "+f"(d[1]), "+f"(d[2]), "+f"(d[3])
        : "r"(a[0]), "r"(a[1]), "r"(a[2]), "r"(a[3]), "r"(b[0]), "r"(b[1]));
}

// ---------------------------------------------------------------------------
// Prep kernels
// ---------------------------------------------------------------------------
__global__ __launch_bounds__(256) void xT_round_kernel(const float* __restrict__ x)
{
    __shared__ float t[32][33];
    const int b  = blockIdx.z;
    const int n0 = blockIdx.x * 32, c0 = blockIdx.y * 32;
    const int tx = threadIdx.x & 31, ty = threadIdx.x >> 5;
    const float* xb = x + (size_t)b * CC * NN;
    #pragma unroll
    for (int i = 0; i < 32; i += 8)
        t[ty + i][tx] = xb[(size_t)(c0 + ty + i) * NN + n0 + tx];
    __syncthreads();
    float* o = g_xT + (size_t)b * NN * CC;
    #pragma unroll
    for (int i = 0; i < 32; i += 8)
        o[(size_t)(n0 + ty + i) * CC + c0 + tx] = tf32r(t[tx][ty + i]);
}

__global__ __launch_bounds__(256) void w_round_kernel(const float* __restrict__ W)
{
    int i = blockIdx.x * 256 + threadIdx.x;
    g_wr[i] = tf32r(W[i]);
}

__global__ __launch_bounds__(256) void wqk_prep_kernel(
    const float* __restrict__ Wq, const float* __restrict__ bq,
    const float* __restrict__ Wk, const float* __restrict__ bk)
{
    int i = blockIdx.x * 256 + threadIdx.x;     // over 128*512
    int r = i >> 9, c = i & 511;
    g_wqk[i] = tf32r(r < DD ? Wq[(size_t)r * CC + c] : Wk[(size_t)(r - DD) * CC + c]);
    if (i < QK) g_bqk[i] = (i < DD) ? bq[i] : bk[i - DD];
}

// ---------------------------------------------------------------------------
// Projection GEMM (TMA + mma.sync tf32), C[m][n] = sum_k A[m][k]*B[n][k]
// mode 0: out = tf32(C + bias[row]);  mode 3: out = tf32(C + bias[col])
// ---------------------------------------------------------------------------
constexpr int BM = 256, BN = 128, BK = 32;
constexpr int NSTAGE = 3;
constexpr int A_BY = BM * BK * 4;
constexpr int B_BY = BN * BK * 4;
constexpr int STAGE_BY = A_BY + B_BY;
constexpr int GEMM_DSMEM = NSTAGE * STAGE_BY + 1024;

__global__ __launch_bounds__(544)
void gemm_kernel(const __grid_constant__ CUtensorMap tma_a,
                 const __grid_constant__ CUtensorMap tma_b,
                 int k_total, int mode, int a_batched, int b_batched,
                 const float* __restrict__ aux,
                 float* __restrict__ outp, size_t out_bstride, int out_rstride)
{
    __shared__ __align__(8) uint64_t s_bar[2 * NSTAGE];
    extern __shared__ char dsm[];
    const uint32_t dbase = (smem_to_u32(dsm) + 1023) & ~1023u;
    const uint32_t sbar  = smem_to_u32(s_bar);

    const int tid = threadIdx.x, wid = tid >> 5, lid = tid & 31;
    const int mBase = blockIdx.y * BM;
    const int nBase = blockIdx.x * BN;
    const int b     = blockIdx.z;
    const int nchunk = k_total / BK;

    if (tid == 0) {
        #pragma unroll
        for (int s = 0; s < NSTAGE; s++) {
            MBARRIER_INIT(sbar + s * 16, 1);
            MBARRIER_INIT(sbar + s * 16 + 8, 16);
        }
    }
    __syncthreads();

    if (tid == 512) {
        const int az = a_batched ? b : 0;
        const int bz = b_batched ? b : 0;
        int ph = 1, st = 0;
        for (int c = 0; c < nchunk; c++) {
            MBARRIER_WAIT_PARITY(sbar + st * 16 + 8, ph);
            MBARRIER_EXPECT_TX(sbar + st * 16, STAGE_BY);
            TMA_LOAD_3D(dbase + st * STAGE_BY,        &tma_a, c * BK, mBase, az, sbar + st * 16);
            TMA_LOAD_3D(dbase + st * STAGE_BY + A_BY, &tma_b, c * BK, nBase, bz, sbar + st * 16);
            if (++st == NSTAGE) { st = 0; ph ^= 1; }
        }
    }

    if (wid < 16) {
        const int wm = wid & 3, wn = wid >> 2;
        const int mWarp = wm * 64, nWarp = wn * 32;
        const int laneA = lid & 15;
        const int hAu   = (lid >> 4) & 1;
        const int laneB = (lid & 7) + ((lid & 16) ? 8 : 0);
        const int hBu   = (lid >> 3) & 1;
        const int xor7  = lid & 7;

        float cacc[4][4][4] = {};

        int ph = 0, st = 0;
        for (int c = 0; c < nchunk; c++) {
            MBARRIER_WAIT_PARITY(sbar + st * 16, ph);
            const uint32_t Ab = dbase + st * STAGE_BY;
            const uint32_t Bb = Ab + A_BY;
            const uint32_t aRowAddr = Ab + (mWarp + laneA) * 128;
            const uint32_t bRowAddr = Bb + (nWarp + laneB) * 128;

            #pragma unroll
            for (int ks = 0; ks < BK / 8; ks++) {
                uint32_t af[4][4];
                uint32_t bf[4][2];
                const uint32_t cA = (uint32_t)(((2 * ks + hAu) ^ xor7) << 4);
                const uint32_t cB = (uint32_t)(((2 * ks + hBu) ^ xor7) << 4);
                #pragma unroll
                for (int mt = 0; mt < 4; mt++)
                    LDSM_X4(af[mt][0], af[mt][1], af[mt][2], af[mt][3],
                            aRowAddr + mt * (16 * 128) + cA);
                #pragma unroll
                for (int p = 0; p < 2; p++) {
                    uint32_t r0, r1, r2, r3;
                    LDSM_X4(r0, r1, r2, r3, bRowAddr + p * (16 * 128) + cB);
                    bf[2*p][0] = r0; bf[2*p][1] = r1;
                    bf[2*p+1][0] = r2; bf[2*p+1][1] = r3;
                }
                #pragma unroll
                for (int mt = 0; mt < 4; mt++)
                    #pragma unroll
                    for (int nt = 0; nt < 4; nt++)
                        mma_tf32(cacc[mt][nt], af[mt], bf[nt]);
            }
            if (lid == 0) MBARRIER_ARRIVE(sbar + st * 16 + 8);
            if (++st == NSTAGE) { st = 0; ph ^= 1; }
        }

        const int g = lid >> 2, t4 = lid & 3;
        float* ob = outp + (size_t)b * out_bstride;

        #pragma unroll
        for (int mt = 0; mt < 4; mt++) {
            const int r0 = mBase + mWarp + mt * 16 + g;
            const int r1 = r0 + 8;
            float bias0 = 0.f, bias1 = 0.f;
            if (mode == 0) { bias0 = aux[r0]; bias1 = aux[r1]; }
            #pragma unroll
            for (int nt = 0; nt < 4; nt++) {
                const int col = nBase + nWarp + nt * 8 + t4 * 2;
                float v00 = cacc[mt][nt][0], v01 = cacc[mt][nt][1];
                float v10 = cacc[mt][nt][2], v11 = cacc[mt][nt][3];
                if (mode == 0) {
                    v00 = tf32r(v00 + bias0); v01 = tf32r(v01 + bias0);
                    v10 = tf32r(v10 + bias1); v11 = tf32r(v11 + bias1);
                } else {    // mode 3
                    const float bc0 = aux[col], bc1 = aux[col + 1];
                    v00 = tf32r(v00 + bc0); v01 = tf32r(v01 + bc1);
                    v10 = tf32r(v10 + bc0); v11 = tf32r(v11 + bc1);
                }
                *(float2*)&ob[(size_t)r0 * out_rstride + col] = make_float2(v00, v01);
                *(float2*)&ob[(size_t)r1 * out_rstride + col] = make_float2(v10, v11);
            }
        }
    }
}

// ---------------------------------------------------------------------------
// Fused attention: per CTA i-tile 128, c-half 256, loop j in chunks of 64.
// S = Q·K^T -> e = tf32(exp(S)) -> SMEM -> O += V·e^T ; rowsums in regs.
// Epilogue: out = gamma*O/rs + x.   No g_att, no atomics to DRAM.
// ---------------------------------------------------------------------------
constexpr int JT = 64;
constexpr int F_Q_OFF  = 0;        // 2 tiles [128][32] = 32 KB
constexpr int F_E_OFF  = 32768;    // 2 tiles [128][32] = 32 KB
constexpr int F_ST_OFF = 65536;
constexpr int F_K_BY   = 16384;    // 2 tiles [64][32]
constexpr int F_STG_BY = F_K_BY + 65536;   // + V: 2 tiles [256][32] = 80 KB
constexpr int F_DSMEM  = F_ST_OFF + 2 * F_STG_BY + 1024;   // 230400

__global__ __launch_bounds__(512)
void fused_attn_kernel(const __grid_constant__ CUtensorMap tmQ,
                       const __grid_constant__ CUtensorMap tmK,
                       const __grid_constant__ CUtensorMap tmV,
                       const float* __restrict__ x,
                       const float* __restrict__ gamma,
                       float* __restrict__ outp)
{
    __shared__ __align__(8) uint64_t s_bar[3];
    __shared__ float rs_s[128];
    extern __shared__ char dsm[];
    const uint32_t dbase = (smem_to_u32(dsm) + 1023) & ~1023u;
    const uint32_t sbar  = smem_to_u32(s_bar);

    const int tid = threadIdx.x, wid = tid >> 5, lid = tid & 31;
    const int cBase = blockIdx.x * 256;
    const int iBase = blockIdx.y * 128;
    const int b     = blockIdx.z;

    const int laneA = lid & 15, hAu = (lid >> 4) & 1;
    const int laneB = (lid & 7) + ((lid & 16) ? 8 : 0), hBu = (lid >> 3) & 1;
    const int xor7  = lid & 7;
    const int g = lid >> 2, t4 = lid & 3;
    const int wm = wid & 3, wn = wid >> 2;

    if (tid == 0) {
        MBARRIER_INIT(sbar, 1);          // Q
        MBARRIER_INIT(sbar + 8, 1);      // stage 0
        MBARRIER_INIT(sbar + 16, 1);     // stage 1
    }
    if (tid < 128) rs_s[tid] = 0.f;
    __syncthreads();

    if (tid == 0) {
        MBARRIER_EXPECT_TX(sbar, 32768);
        TMA_LOAD_3D(dbase + F_Q_OFF,         &tmQ, 0,  iBase, b, sbar);
        TMA_LOAD_3D(dbase + F_Q_OFF + 16384, &tmQ, 32, iBase, b, sbar);
        #pragma unroll
        for (int c = 0; c < 2; c++) {
            const uint32_t sb = dbase + F_ST_OFF + c * F_STG_BY;
            MBARRIER_EXPECT_TX(sbar + 8 + c * 8, F_STG_BY);
            TMA_LOAD_3D(sb,                  &tmK, DD,          c * JT, b, sbar + 8 + c * 8);
            TMA_LOAD_3D(sb + 8192,           &tmK, DD + 32,     c * JT, b, sbar + 8 + c * 8);
            TMA_LOAD_3D(sb + F_K_BY,         &tmV, c * JT,      cBase,  b, sbar + 8 + c * 8);
            TMA_LOAD_3D(sb + F_K_BY + 32768, &tmV, c * JT + 32, cBase,  b, sbar + 8 + c * 8);
        }
    }
    MBARRIER_WAIT_PARITY(sbar, 0);

    float oacc[4][4][4] = {};
    float rs_p[2][2] = {};

    const uint32_t qRow = dbase + F_Q_OFF + (wm * 32 + laneA) * 128;
    const int NCH = NN / JT;

    for (int ch = 0; ch < NCH; ch++) {
        const int s = ch & 1, ph = (ch >> 1) & 1;
        MBARRIER_WAIT_PARITY(sbar + 8 + s * 8, ph);
        const uint32_t SB = dbase + F_ST_OFF + s * F_STG_BY;

        // ---- S phase: S[128i x 64j], K-dim = d = 64
        float sacc[2][2][4] = {};
        const uint32_t kRow = SB + (wn * 16 + laneB) * 128;
        #pragma unroll
        for (int ks = 0; ks < 8; ks++) {
            const int tsel = ks >> 2, ksl = ks & 3;
            const uint32_t cA = (uint32_t)(((2 * ksl + hAu) ^ xor7) << 4);
            const uint32_t cB = (uint32_t)(((2 * ksl + hBu) ^ xor7) << 4);
            uint32_t af[2][4]; uint32_t bf[2][2];
            LDSM_X4(af[0][0], af[0][1], af[0][2], af[0][3], qRow + tsel * 16384 + cA);
            LDSM_X4(af[1][0], af[1][1], af[1][2], af[1][3], qRow + tsel * 16384 + 2048 + cA);
            { uint32_t r0, r1, r2, r3;
              LDSM_X4(r0, r1, r2, r3, kRow + tsel * 8192 + cB);
              bf[0][0] = r0; bf[0][1] = r1; bf[1][0] = r2; bf[1][1] = r3; }
            #pragma unroll
            for (int mt = 0; mt < 2; mt++)
                #pragma unroll
                for (int nt = 0; nt < 2; nt++)
                    mma_tf32(sacc[mt][nt], af[mt], bf[nt]);
        }

        // ---- exp + rowsum partials + e -> SMEM (TMA-mirrored swizzle)
        #pragma unroll
        for (int mt = 0; mt < 2; mt++) {
            const int r0 = wm * 32 + mt * 16 + g;
            #pragma unroll
            for (int nt = 0; nt < 2; nt++) {
                const int jc = wn * 16 + nt * 8 + t4 * 2;
                const int tt = jc >> 5, c32 = jc & 31;
                const float e00 = tf32r(__expf(sacc[mt][nt][0]));
                const float e01 = tf32r(__expf(sacc[mt][nt][1]));
                const float e10 = tf32r(__expf(sacc[mt][nt][2]));
                const float e11 = tf32r(__expf(sacc[mt][nt][3]));
                rs_p[mt][0] += e00 + e01;
                rs_p[mt][1] += e10 + e11;
                const uint32_t go = (((uint32_t)(c32 >> 2) ^ (uint32_t)(r0 & 7)) << 4)
                                    + (uint32_t)(c32 & 3) * 4;
                const uint32_t a0 = dbase + F_E_OFF + tt * 16384 + r0 * 128 + go;
                asm volatile("st.shared.v2.f32 [%0], {%1,%2};" :: "r"(a0), "f"(e00), "f"(e01));
                asm volatile("st.shared.v2.f32 [%0], {%1,%2};" :: "r"(a0 + 1024), "f"(e10), "f"(e11));
            }
        }
        __syncthreads();   // e visible to all; K[s] reads done

        // ---- AV phase: O[256c x 128i] += V·e^T, K-dim = j = 64
        const uint32_t vRow = SB + F_K_BY + (wm * 64 + laneA) * 128;
        const uint32_t eRow = dbase + F_E_OFF + (wn * 32 + laneB) * 128;
        #pragma unroll
        for (int ks = 0; ks < 8; ks++) {
            const int tsel = ks >> 2, ksl = ks & 3;
            const uint32_t cA = (uint32_t)(((2 * ksl + hAu) ^ xor7) << 4);
            const uint32_t cB = (uint32_t)(((2 * ksl + hBu) ^ xor7) << 4);
            uint32_t af[4][4]; uint32_t bf[4][2];
            #pragma unroll
            for (int mt = 0; mt < 4; mt++)
                LDSM_X4(af[mt][0], af[mt][1], af[mt][2], af[mt][3],
                        vRow + tsel * 32768 + mt * 2048 + cA);
            #pragma unroll
            for (int p = 0; p < 2; p++) {
                uint32_t r0, r1, r2, r3;
                LDSM_X4(r0, r1, r2, r3, eRow + tsel * 16384 + p * 2048 + cB);
                bf[2*p][0] = r0; bf[2*p][1] = r1;
                bf[2*p+1][0] = r2; bf[2*p+1][1] = r3;
            }
            #pragma unroll
            for (int mt = 0; mt < 4; mt++)
                #pragma unroll
                for (int nt = 0; nt < 4; nt++)
                    mma_tf32(oacc[mt][nt], af[mt], bf[nt]);
        }
        __syncthreads();   // V[s] + e consumed -> stage free

        if (tid == 0 && ch + 2 < NCH) {
            const int cn = ch + 2;
            MBARRIER_EXPECT_TX(sbar + 8 + s * 8, F_STG_BY);
            TMA_LOAD_3D(SB,                  &tmK, DD,           cn * JT, b, sbar + 8 + s * 8);
            TMA_LOAD_3D(SB + 8192,           &tmK, DD + 32,      cn * JT, b, sbar + 8 + s * 8);
            TMA_LOAD_3D(SB + F_K_BY,         &tmV, cn * JT,      cBase,   b, sbar + 8 + s * 8);
            TMA_LOAD_3D(SB + F_K_BY + 32768, &tmV, cn * JT + 32, cBase,   b, sbar + 8 + s * 8);
        }
    }

    // ---- rowsum reduce (S-phase coordinates)
    #pragma unroll
    for (int mt = 0; mt < 2; mt++) {
        float s0 = rs_p[mt][0], s1 = rs_p[mt][1];
        s0 += __shfl_xor_sync(~0u, s0, 1); s0 += __shfl_xor_sync(~0u, s0, 2);
        s1 += __shfl_xor_sync(~0u, s1, 1); s1 += __shfl_xor_sync(~0u, s1, 2);
        if (t4 == 0) {
            atomicAdd(&rs_s[wm * 32 + mt * 16 + g],     s0);
            atomicAdd(&rs_s[wm * 32 + mt * 16 + g + 8], s1);
        }
    }
    __syncthreads();

    // ---- epilogue: out = gamma * O / rs + x
    const float gm = gamma[0];
    const float* xb = x + (size_t)b * CC * NN;
    float* ob = outp + (size_t)b * CC * NN;
    #pragma unroll
    for (int mt = 0; mt < 4; mt++) {
        const int c0 = cBase + wm * 64 + mt * 16 + g;
        const int c1 = c0 + 8;
        #pragma unroll
        for (int nt = 0; nt < 4; nt++) {
            const int il = wn * 32 + nt * 8 + t4 * 2;
            const float i0 = __fdividef(1.f, rs_s[il]);
            const float i1 = __fdividef(1.f, rs_s[il + 1]);
            const int gi = iBase + il;
            const float2 x0 = *(const float2*)&xb[(size_t)c0 * NN + gi];
            const float2 x1 = *(const float2*)&xb[(size_t)c1 * NN + gi];
            *(float2*)&ob[(size_t)c0 * NN + gi] =
                make_float2(gm * oacc[mt][nt][0] * i0 + x0.x,
                            gm * oacc[mt][nt][1] * i1 + x0.y);
            *(float2*)&ob[(size_t)c1 * NN + gi] =
                make_float2(gm * oacc[mt][nt][2] * i0 + x1.x,
                            gm * oacc[mt][nt][3] * i1 + x1.y);
        }
    }
}

// ---------------------------------------------------------------------------
// Host side
// ---------------------------------------------------------------------------
typedef CUresult (*EncodeFn)(CUtensorMap*, CUtensorMapDataType, cuuint32_t, void*,
                             const cuuint64_t*, const cuuint64_t*, const cuuint32_t*,
                             const cuuint32_t*, CUtensorMapInterleave, CUtensorMapSwizzle,
                             CUtensorMapL2promotion, CUtensorMapFloatOOBfill);

static void build_tm(EncodeFn enc, CUtensorMap* tm, void* ptr,
                     uint64_t d0, uint64_t d1, uint64_t d2,
                     uint64_t s1b, uint64_t s2b, uint32_t b0, uint32_t b1)
{
    cuuint64_t dims[3] = {d0, d1, d2};
    cuuint64_t str[2]  = {s1b, s2b};
    cuuint32_t box[3]  = {b0, b1, 1};
    cuuint32_t es[3]   = {1, 1, 1};
    enc(tm, CU_TENSOR_MAP_DATA_TYPE_FLOAT32, 3, ptr, dims, str, box, es,
        CU_TENSOR_MAP_INTERLEAVE_NONE, CU_TENSOR_MAP_SWIZZLE_128B,
        CU_TENSOR_MAP_L2_PROMOTION_L2_128B, CU_TENSOR_MAP_FLOAT_OOB_FILL_NONE);
}

extern "C" void kernel_launch(void* const* d_in, const int* in_sizes, int n_in,
                              void* d_out, int out_size)
{
    (void)in_sizes; (void)n_in; (void)out_size;
    const float* x     = (const float*)d_in[0];
    const float* Wq    = (const float*)d_in[1];
    const float* bq    = (const float*)d_in[2];
    const float* Wk    = (const float*)d_in[3];
    const float* bk    = (const float*)d_in[4];
    const float* Wv    = (const float*)d_in[5];
    const float* bv    = (const float*)d_in[6];
    const float* gamma = (const float*)d_in[7];
    float* out = (float*)d_out;

    EncodeFn enc = nullptr;
    cudaDriverEntryPointQueryResult qr;
    cudaGetDriverEntryPointByVersion("cuTensorMapEncodeTiled", (void**)&enc, 12000,
                                     cudaEnableDefault, &qr);

    void *pqk, *pv, *pxT, *pwr, *pwqk, *pbqk;
    cudaGetSymbolAddress(&pqk,  g_qk);
    cudaGetSymbolAddress(&pv,   g_v);
    cudaGetSymbolAddress(&pxT,  g_xT);
    cudaGetSymbolAddress(&pwr,  g_wr);
    cudaGetSymbolAddress(&pwqk, g_wqk);
    cudaGetSymbolAddress(&pbqk, g_bqk);

    CUtensorMap tmXT_A, tmXT_B, tmWQK, tmWV, tmQ, tmK, tmV;
    build_tm(enc, &tmXT_A, pxT, CC, NN, BB, (uint64_t)CC * 4, (uint64_t)NN * CC * 4, 32, 256);
    build_tm(enc, &tmXT_B, pxT, CC, NN, BB, (uint64_t)CC * 4, (uint64_t)NN * CC * 4, 32, 128);
    build_tm(enc, &tmWQK, pwqk, CC, QK, 1, (uint64_t)CC * 4, (uint64_t)QK * CC * 4, 32, 128);
    build_tm(enc, &tmWV, pwr, CC, CC, 1, (uint64_t)CC * 4, (uint64_t)CC * CC * 4, 32, 256);
    // fused attention maps over g_qk / g_v
    build_tm(enc, &tmQ, pqk, QK, NN, BB, (uint64_t)QK * 4, (uint64_t)NN * QK * 4, 32, 128);
    build_tm(enc, &tmK, pqk, QK, NN, BB, (uint64_t)QK * 4, (uint64_t)NN * QK * 4, 32, 64);
    build_tm(enc, &tmV, pv,  NN, CC, BB, (uint64_t)NN * 4, (uint64_t)CC * NN * 4, 32, 256);

    cudaFuncSetAttribute(gemm_kernel, cudaFuncAttributeMaxDynamicSharedMemorySize, GEMM_DSMEM);
    cudaFuncSetAttribute(fused_attn_kernel, cudaFuncAttributeMaxDynamicSharedMemorySize, F_DSMEM);

    // 1. prep
    xT_round_kernel<<<dim3(NN / 32, CC / 32, BB), 256>>>(x);
    w_round_kernel<<<(CC * CC) / 256, 256>>>(Wv);
    wqk_prep_kernel<<<(QK * CC) / 256, 256>>>(Wq, bq, Wk, bk);
    // 2. qk projection: g_qk[n][d] = xT·wqk^T + bqk[d], K=512
    gemm_kernel<<<dim3(QK / BN, NN / BM, BB), 544, GEMM_DSMEM>>>(
        tmXT_A, tmWQK, CC, 3, 1, 0, (const float*)pbqk,
        (float*)pqk, (size_t)NN * QK, QK);
    // 3. v projection: g_v[c][n] = wr·xT^T + bv[c], K=512
    gemm_kernel<<<dim3(NN / BN, CC / BM, BB), 544, GEMM_DSMEM>>>(
        tmWV, tmXT_B, CC, 0, 0, 1, bv,
        (float*)pv, (size_t)CC * NN, NN);
    // 4. fused attention: scores + exp + rowsum + AV + epilogue
    fused_attn_kernel<<<dim3(2, NN / 128, BB), 512, F_DSMEM>>>(
        tmQ, tmK, tmV, x, gamma, out);
}

// round 8
// speedup vs baseline: 1.2166x; 1.2166x over previous
#include <cuda_runtime.h>
#include <cuda.h>
#include <cuda_fp16.h>
#include <cstdint>
#include <math.h>

constexpr int BB = 2;
constexpr int CC = 512;
constexpr int NN = 4096;
constexpr int DD = 64;
constexpr int QK = 128;

// ---------------------------------------------------------------------------
// Scratch
// ---------------------------------------------------------------------------
__device__ __align__(1024) __half g_qkh[(size_t)BB * NN * QK];  // [b][n][q|k] fp16
__device__ __align__(1024) float  g_v  [(size_t)BB * CC * NN];  // [b][c][j] tf32
__device__ __align__(1024) __half g_xTh[(size_t)BB * NN * CC];  // [b][n][c] fp16
__device__ __align__(1024) __half g_wrh[(size_t)CC * CC];       // Wv fp16
__device__ __align__(1024) __half g_wqkh[(size_t)QK * CC];      // Wq|Wk fp16
__device__ __align__(1024) float  g_bqk[QK];
__device__ __align__(1024) float  g_att[(size_t)BB * NN * NN];  // e = tf32(exp(s))
__device__ __align__(1024) float  g_rs [(size_t)BB * NN];       // row sums

// ---------------------------------------------------------------------------
// PTX helpers
// ---------------------------------------------------------------------------
__device__ __forceinline__ uint32_t smem_to_u32(const void* p) {
    uint32_t a;
    asm("{ .reg .u64 t; cvta.to.shared.u64 t, %1; cvt.u32.u64 %0, t; }"
        : "=r"(a) : "l"(p));
    return a;
}
__device__ __forceinline__ float tf32r(float v) {
    uint32_t o;
    asm("cvt.rna.tf32.f32 %0, %1;" : "=r"(o) : "f"(v));
    return __uint_as_float(o);
}

#define MBARRIER_INIT(addr, cnt) \
    asm volatile("mbarrier.init.shared.b64 [%0], %1;" \
        :: "r"((uint32_t)(addr)), "r"((uint32_t)(cnt)) : "memory")
#define MBARRIER_EXPECT_TX(addr, bytes) \
    asm volatile("mbarrier.arrive.expect_tx.shared.b64 _, [%0], %1;" \
        :: "r"((uint32_t)(addr)), "r"((uint32_t)(bytes)) : "memory")
#define MBARRIER_ARRIVE(addr) \
    asm volatile("mbarrier.arrive.shared.b64 _, [%0];" \
        :: "r"((uint32_t)(addr)) : "memory")
#define MBARRIER_WAIT_PARITY(addr, parity) do { \
    uint32_t _m = (uint32_t)(addr); uint32_t _p = (uint32_t)(parity); uint32_t _d; \
    asm volatile("{\n\t.reg .pred p;\n\t" \
        "mbarrier.try_wait.parity.shared.b64 p, [%1], %2;\n\t" \
        "selp.b32 %0, 1, 0, p;\n\t}" : "=r"(_d) : "r"(_m), "r"(_p) : "memory"); \
    if (!_d) { \
        asm volatile("{\n\t.reg .pred P1;\n\tWL_%=:\n\t" \
            "mbarrier.try_wait.parity.shared.b64 P1, [%0], %1, 0x989680;\n\t" \
            "@P1 bra.uni WD_%=;\n\tbra.uni WL_%=;\n\tWD_%=:\n\t}" \
            :: "r"(_m), "r"(_p) : "memory"); \
    } } while (0)

#define TMA_LOAD_3D(smem_addr, tmap, cx, cy, cz, mbar) \
    asm volatile( \
        "cp.async.bulk.tensor.3d.shared::cta.global.tile.mbarrier::complete_tx::bytes " \
        "[%0], [%1, {%2, %3, %4}], [%5];" \
        :: "r"((uint32_t)(smem_addr)), "l"(tmap), \
           "r"((int32_t)(cx)), "r"((int32_t)(cy)), "r"((int32_t)(cz)), \
           "r"((uint32_t)(mbar)) : "memory")

#define LDSM_X4(r0, r1, r2, r3, addr) \
    asm volatile("ldmatrix.sync.aligned.m8n8.x4.shared.b16 {%0,%1,%2,%3}, [%4];" \
        : "=r"(r0), "=r"(r1), "=r"(r2), "=r"(r3) : "r"(addr))

__device__ __forceinline__ void mma_tf32(float* d, const uint32_t* a, const uint32_t* b) {
    asm volatile(
        "mma.sync.aligned.m16n8k8.row.col.f32.tf32.tf32.f32 "
        "{%0,%1,%2,%3}, {%4,%5,%6,%7}, {%8,%9}, {%0,%1,%2,%3};"
        : "+f"(d[0]), "+f"(d[1]), "+f"(d[2]), "+f"(d[3])
        : "r"(a[0]), "r"(a[1]), "r"(a[2]), "r"(a[3]), "r"(b[0]), "r"(b[1]));
}
__device__ __forceinline__ void mma_f16(float* d, const uint32_t* a, const uint32_t* b) {
    asm volatile(
        "mma.sync.aligned.m16n8k16.row.col.f32.f16.f16.f32 "
        "{%0,%1,%2,%3}, {%4,%5,%6,%7}, {%8,%9}, {%0,%1,%2,%3};"
        : "+f"(d[0]), "+f"(d[1]), "+f"(d[2]), "+f"(d[3])
        : "r"(a[0]), "r"(a[1]), "r"(a[2]), "r"(a[3]), "r"(b[0]), "r"(b[1]));
}

// ---------------------------------------------------------------------------
// Prep kernels
// ---------------------------------------------------------------------------
__global__ __launch_bounds__(256) void xT_half_kernel(const float* __restrict__ x)
{
    __shared__ float t[32][33];
    const int b  = blockIdx.z;
    const int n0 = blockIdx.x * 32, c0 = blockIdx.y * 32;
    const int tx = threadIdx.x & 31, ty = threadIdx.x >> 5;
    const float* xb = x + (size_t)b * CC * NN;
    #pragma unroll
    for (int i = 0; i < 32; i += 8)
        t[ty + i][tx] = xb[(size_t)(c0 + ty + i) * NN + n0 + tx];
    __syncthreads();
    __half* o = g_xTh + (size_t)b * NN * CC;
    #pragma unroll
    for (int i = 0; i < 32; i += 8)
        o[(size_t)(n0 + ty + i) * CC + c0 + tx] = __float2half_rn(t[tx][ty + i]);
}

__global__ __launch_bounds__(256) void w_half_kernel(const float* __restrict__ W)
{
    int i = blockIdx.x * 256 + threadIdx.x;
    g_wrh[i] = __float2half_rn(W[i]);
}

// Stack Wq|Wk -> fp16, stack biases, zero row sums
__global__ __launch_bounds__(256) void wqk_prep_kernel(
    const float* __restrict__ Wq, const float* __restrict__ bq,
    const float* __restrict__ Wk, const float* __restrict__ bk)
{
    int i = blockIdx.x * 256 + threadIdx.x;     // 128*512 = 65536 threads
    int r = i >> 9, c = i & 511;
    g_wqkh[i] = __float2half_rn(r < DD ? Wq[(size_t)r * CC + c]
                                       : Wk[(size_t)(r - DD) * CC + c]);
    if (i < QK) g_bqk[i] = (i < DD) ? bq[i] : bk[i - DD];
    if (i < BB * NN) g_rs[i] = 0.0f;
}

// ---------------------------------------------------------------------------
// fp16 GEMM: C[m][n] = sum_k A[m][k]*B[n][k], fp32 accum.
// Tile 256x128, BK=64 halves (128B rows). 16 consumer warps + 1 producer.
// mode 0: fp32 out = tf32r(C + bias[row])          (v-proj)
// mode 2: fp32 out = tf32r(exp(C)); rowsum atomics  (scores)
// mode 3: half out = C + bias[col]                  (qk-proj)
// ---------------------------------------------------------------------------
constexpr int BM = 256, BN = 128;
constexpr int NSTAGE = 3;
constexpr int A16_BY = BM * 128;                  // 32 KB
constexpr int B16_BY = BN * 128;                  // 16 KB
constexpr int STG16_BY = A16_BY + B16_BY;         // 48 KB
constexpr int G16_DSMEM = NSTAGE * STG16_BY + 1024;

__global__ __launch_bounds__(544)
void gemm16_kernel(const __grid_constant__ CUtensorMap tma_a,
                   const __grid_constant__ CUtensorMap tma_b,
                   int k_total, int mode, int a_batched, int b_batched,
                   int a_koff, int b_koff,
                   const float* __restrict__ aux,
                   float* __restrict__ rs,
                   void* __restrict__ outp, size_t out_bstride, int out_rstride)
{
    __shared__ __align__(8) uint64_t s_bar[2 * NSTAGE];
    extern __shared__ char dsm[];
    const uint32_t dbase = (smem_to_u32(dsm) + 1023) & ~1023u;
    const uint32_t sbar  = smem_to_u32(s_bar);

    const int tid = threadIdx.x, wid = tid >> 5, lid = tid & 31;
    const int mBase = blockIdx.y * BM;
    const int nBase = blockIdx.x * BN;
    const int b     = blockIdx.z;
    const int nchunk = k_total / 64;

    if (tid == 0) {
        #pragma unroll
        for (int s = 0; s < NSTAGE; s++) {
            MBARRIER_INIT(sbar + s * 16, 1);
            MBARRIER_INIT(sbar + s * 16 + 8, 16);
        }
    }
    __syncthreads();

    if (tid == 512) {
        const int az = a_batched ? b : 0;
        const int bz = b_batched ? b : 0;
        int ph = 1, st = 0;
        for (int c = 0; c < nchunk; c++) {
            MBARRIER_WAIT_PARITY(sbar + st * 16 + 8, ph);
            MBARRIER_EXPECT_TX(sbar + st * 16, STG16_BY);
            TMA_LOAD_3D(dbase + st * STG16_BY,          &tma_a, a_koff + c * 64, mBase, az, sbar + st * 16);
            TMA_LOAD_3D(dbase + st * STG16_BY + A16_BY, &tma_b, b_koff + c * 64, nBase, bz, sbar + st * 16);
            if (++st == NSTAGE) { st = 0; ph ^= 1; }
        }
    }

    if (wid < 16) {
        const int wm = wid & 3, wn = wid >> 2;
        const int mWarp = wm * 64, nWarp = wn * 32;
        const int laneA = lid & 15;
        const int hAu   = (lid >> 4) & 1;
        const int laneB = (lid & 7) + ((lid & 16) ? 8 : 0);
        const int hBu   = (lid >> 3) & 1;
        const int xor7  = lid & 7;

        float cacc[4][4][4] = {};

        int ph = 0, st = 0;
        for (int c = 0; c < nchunk; c++) {
            MBARRIER_WAIT_PARITY(sbar + st * 16, ph);
            const uint32_t Ab = dbase + st * STG16_BY;
            const uint32_t Bb = Ab + A16_BY;
            const uint32_t aRowAddr = Ab + (mWarp + laneA) * 128;
            const uint32_t bRowAddr = Bb + (nWarp + laneB) * 128;

            #pragma unroll
            for (int ks = 0; ks < 4; ks++) {        // 4 x k16
                uint32_t af[4][4];
                uint32_t bf[4][2];
                const uint32_t cA = (uint32_t)(((2 * ks + hAu) ^ xor7) << 4);
                const uint32_t cB = (uint32_t)(((2 * ks + hBu) ^ xor7) << 4);
                #pragma unroll
                for (int mt = 0; mt < 4; mt++)
                    LDSM_X4(af[mt][0], af[mt][1], af[mt][2], af[mt][3],
                            aRowAddr + mt * (16 * 128) + cA);
                #pragma unroll
                for (int p = 0; p < 2; p++) {
                    uint32_t r0, r1, r2, r3;
                    LDSM_X4(r0, r1, r2, r3, bRowAddr + p * (16 * 128) + cB);
                    bf[2*p][0] = r0; bf[2*p][1] = r1;
                    bf[2*p+1][0] = r2; bf[2*p+1][1] = r3;
                }
                #pragma unroll
                for (int mt = 0; mt < 4; mt++)
                    #pragma unroll
                    for (int nt = 0; nt < 4; nt++)
                        mma_f16(cacc[mt][nt], af[mt], bf[nt]);
            }
            if (lid == 0) MBARRIER_ARRIVE(sbar + st * 16 + 8);
            if (++st == NSTAGE) { st = 0; ph ^= 1; }
        }

        // ---- epilogue ----
        const int g = lid >> 2, t4 = lid & 3;
        float* rs_b = rs + (size_t)b * NN;

        #pragma unroll
        for (int mt = 0; mt < 4; mt++) {
            const int r0 = mBase + mWarp + mt * 16 + g;
            const int r1 = r0 + 8;
            float bias0 = 0.f, bias1 = 0.f;
            if (mode == 0) { bias0 = aux[r0]; bias1 = aux[r1]; }
            float s0 = 0.f, s1 = 0.f;
            #pragma unroll
            for (int nt = 0; nt < 4; nt++) {
                const int col = nBase + nWarp + nt * 8 + t4 * 2;
                float v00 = cacc[mt][nt][0], v01 = cacc[mt][nt][1];
                float v10 = cacc[mt][nt][2], v11 = cacc[mt][nt][3];
                if (mode == 3) {
                    const float bc0 = aux[col], bc1 = aux[col + 1];
                    __half* ob = (__half*)outp + (size_t)b * out_bstride;
                    *(__half2*)&ob[(size_t)r0 * out_rstride + col] =
                        __floats2half2_rn(v00 + bc0, v01 + bc1);
                    *(__half2*)&ob[(size_t)r1 * out_rstride + col] =
                        __floats2half2_rn(v10 + bc0, v11 + bc1);
                } else {
                    float* ob = (float*)outp + (size_t)b * out_bstride;
                    if (mode == 0) {
                        v00 = tf32r(v00 + bias0); v01 = tf32r(v01 + bias0);
                        v10 = tf32r(v10 + bias1); v11 = tf32r(v11 + bias1);
                    } else {    // mode 2
                        v00 = tf32r(__expf(v00)); v01 = tf32r(__expf(v01));
                        v10 = tf32r(__expf(v10)); v11 = tf32r(__expf(v11));
                        s0 += v00 + v01; s1 += v10 + v11;
                    }
                    *(float2*)&ob[(size_t)r0 * out_rstride + col] = make_float2(v00, v01);
                    *(float2*)&ob[(size_t)r1 * out_rstride + col] = make_float2(v10, v11);
                }
            }
            if (mode == 2) {
                s0 += __shfl_xor_sync(0xFFFFFFFFu, s0, 1);
                s0 += __shfl_xor_sync(0xFFFFFFFFu, s0, 2);
                s1 += __shfl_xor_sync(0xFFFFFFFFu, s1, 1);
                s1 += __shfl_xor_sync(0xFFFFFFFFu, s1, 2);
                if (t4 == 0) {
                    atomicAdd(&rs_b[r0], s0);
                    atomicAdd(&rs_b[r1], s1);
                }
            }
        }
    }
}

// ---------------------------------------------------------------------------
// tf32 AV GEMM: out[c][i] = gamma * (sum_j v[c][j]*e[i][j]) / rs[i] + x[c][i]
// Tile 256(c) x 128(i) x 32(j). Grid: (c-tiles, i-tiles, b) - c fastest for
// e-tile L2 sharing.
// ---------------------------------------------------------------------------
constexpr int BK32 = 32;
constexpr int A32_BY = BM * BK32 * 4;             // 32 KB
constexpr int B32_BY = BN * BK32 * 4;             // 16 KB
constexpr int STG32_BY = A32_BY + B32_BY;
constexpr int G32_DSMEM = NSTAGE * STG32_BY + 1024;

__global__ __launch_bounds__(544)
void av_kernel(const __grid_constant__ CUtensorMap tma_v,
               const __grid_constant__ CUtensorMap tma_e,
               const float* __restrict__ x,
               const float* __restrict__ rs,
               const float* __restrict__ gamma,
               float* __restrict__ outp)
{
    __shared__ __align__(8) uint64_t s_bar[2 * NSTAGE];
    extern __shared__ char dsm[];
    const uint32_t dbase = (smem_to_u32(dsm) + 1023) & ~1023u;
    const uint32_t sbar  = smem_to_u32(s_bar);

    const int tid = threadIdx.x, wid = tid >> 5, lid = tid & 31;
    const int mBase = blockIdx.x * BM;      // c
    const int nBase = blockIdx.y * BN;      // i
    const int b     = blockIdx.z;
    const int nchunk = NN / BK32;

    if (tid == 0) {
        #pragma unroll
        for (int s = 0; s < NSTAGE; s++) {
            MBARRIER_INIT(sbar + s * 16, 1);
            MBARRIER_INIT(sbar + s * 16 + 8, 16);
        }
    }
    __syncthreads();

    if (tid == 512) {
        int ph = 1, st = 0;
        for (int c = 0; c < nchunk; c++) {
            MBARRIER_WAIT_PARITY(sbar + st * 16 + 8, ph);
            MBARRIER_EXPECT_TX(sbar + st * 16, STG32_BY);
            TMA_LOAD_3D(dbase + st * STG32_BY,          &tma_v, c * BK32, mBase, b, sbar + st * 16);
            TMA_LOAD_3D(dbase + st * STG32_BY + A32_BY, &tma_e, c * BK32, nBase, b, sbar + st * 16);
            if (++st == NSTAGE) { st = 0; ph ^= 1; }
        }
    }

    if (wid < 16) {
        const int wm = wid & 3, wn = wid >> 2;
        const int mWarp = wm * 64, nWarp = wn * 32;
        const int laneA = lid & 15;
        const int hAu   = (lid >> 4) & 1;
        const int laneB = (lid & 7) + ((lid & 16) ? 8 : 0);
        const int hBu   = (lid >> 3) & 1;
        const int xor7  = lid & 7;

        float cacc[4][4][4] = {};

        int ph = 0, st = 0;
        for (int c = 0; c < nchunk; c++) {
            MBARRIER_WAIT_PARITY(sbar + st * 16, ph);
            const uint32_t Ab = dbase + st * STG32_BY;
            const uint32_t Bb = Ab + A32_BY;
            const uint32_t aRowAddr = Ab + (mWarp + laneA) * 128;
            const uint32_t bRowAddr = Bb + (nWarp + laneB) * 128;

            #pragma unroll
            for (int ks = 0; ks < 4; ks++) {
                uint32_t af[4][4];
                uint32_t bf[4][2];
                const uint32_t cA = (uint32_t)(((2 * ks + hAu) ^ xor7) << 4);
                const uint32_t cB = (uint32_t)(((2 * ks + hBu) ^ xor7) << 4);
                #pragma unroll
                for (int mt = 0; mt < 4; mt++)
                    LDSM_X4(af[mt][0], af[mt][1], af[mt][2], af[mt][3],
                            aRowAddr + mt * (16 * 128) + cA);
                #pragma unroll
                for (int p = 0; p < 2; p++) {
                    uint32_t r0, r1, r2, r3;
                    LDSM_X4(r0, r1, r2, r3, bRowAddr + p * (16 * 128) + cB);
                    bf[2*p][0] = r0; bf[2*p][1] = r1;
                    bf[2*p+1][0] = r2; bf[2*p+1][1] = r3;
                }
                #pragma unroll
                for (int mt = 0; mt < 4; mt++)
                    #pragma unroll
                    for (int nt = 0; nt < 4; nt++)
                        mma_tf32(cacc[mt][nt], af[mt], bf[nt]);
            }
            if (lid == 0) MBARRIER_ARRIVE(sbar + st * 16 + 8);
            if (++st == NSTAGE) { st = 0; ph ^= 1; }
        }

        const int g = lid >> 2, t4 = lid & 3;
        const float gm = gamma[0];
        const float* rs_b = rs + (size_t)b * NN;
        const float* xb = x + (size_t)b * CC * NN;
        float* ob = outp + (size_t)b * CC * NN;

        #pragma unroll
        for (int mt = 0; mt < 4; mt++) {
            const int r0 = mBase + mWarp + mt * 16 + g;
            const int r1 = r0 + 8;
            #pragma unroll
            for (int nt = 0; nt < 4; nt++) {
                const int col = nBase + nWarp + nt * 8 + t4 * 2;
                const float i0 = __fdividef(1.0f, rs_b[col]);
                const float i1 = __fdividef(1.0f, rs_b[col + 1]);
                const float2 x0 = *(const float2*)&xb[(size_t)r0 * NN + col];
                const float2 x1 = *(const float2*)&xb[(size_t)r1 * NN + col];
                *(float2*)&ob[(size_t)r0 * NN + col] =
                    make_float2(gm * cacc[mt][nt][0] * i0 + x0.x,
                                gm * cacc[mt][nt][1] * i1 + x0.y);
                *(float2*)&ob[(size_t)r1 * NN + col] =
                    make_float2(gm * cacc[mt][nt][2] * i0 + x1.x,
                                gm * cacc[mt][nt][3] * i1 + x1.y);
            }
        }
    }
}

// ---------------------------------------------------------------------------
// Host side
// ---------------------------------------------------------------------------
typedef CUresult (*EncodeFn)(CUtensorMap*, CUtensorMapDataType, cuuint32_t, void*,
                             const cuuint64_t*, const cuuint64_t*, const cuuint32_t*,
                             const cuuint32_t*, CUtensorMapInterleave, CUtensorMapSwizzle,
                             CUtensorMapL2promotion, CUtensorMapFloatOOBfill);

static void build_tm(EncodeFn enc, CUtensorMap* tm, void* ptr, CUtensorMapDataType dt,
                     uint64_t d0, uint64_t d1, uint64_t d2,
                     uint64_t s1b, uint64_t s2b, uint32_t b0, uint32_t b1)
{
    cuuint64_t dims[3] = {d0, d1, d2};
    cuuint64_t str[2]  = {s1b, s2b};
    cuuint32_t box[3]  = {b0, b1, 1};
    cuuint32_t es[3]   = {1, 1, 1};
    enc(tm, dt, 3, ptr, dims, str, box, es,
        CU_TENSOR_MAP_INTERLEAVE_NONE, CU_TENSOR_MAP_SWIZZLE_128B,
        CU_TENSOR_MAP_L2_PROMOTION_L2_128B, CU_TENSOR_MAP_FLOAT_OOB_FILL_NONE);
}

extern "C" void kernel_launch(void* const* d_in, const int* in_sizes, int n_in,
                              void* d_out, int out_size)
{
    (void)in_sizes; (void)n_in; (void)out_size;
    const float* x     = (const float*)d_in[0];
    const float* Wq    = (const float*)d_in[1];
    const float* bq    = (const float*)d_in[2];
    const float* Wk    = (const float*)d_in[3];
    const float* bk    = (const float*)d_in[4];
    const float* Wv    = (const float*)d_in[5];
    const float* bv    = (const float*)d_in[6];
    const float* gamma = (const float*)d_in[7];
    float* out = (float*)d_out;

    EncodeFn enc = nullptr;
    cudaDriverEntryPointQueryResult qr;
    cudaGetDriverEntryPointByVersion("cuTensorMapEncodeTiled", (void**)&enc, 12000,
                                     cudaEnableDefault, &qr);

    void *pqk, *pv, *patt, *pxT, *pwr, *pwqk, *pbqk, *prs;
    cudaGetSymbolAddress(&pqk,  g_qkh);
    cudaGetSymbolAddress(&pv,   g_v);
    cudaGetSymbolAddress(&patt, g_att);
    cudaGetSymbolAddress(&pxT,  g_xTh);
    cudaGetSymbolAddress(&pwr,  g_wrh);
    cudaGetSymbolAddress(&pwqk, g_wqkh);
    cudaGetSymbolAddress(&pbqk, g_bqk);
    cudaGetSymbolAddress(&prs,  g_rs);

    const CUtensorMapDataType H = CU_TENSOR_MAP_DATA_TYPE_FLOAT16;
    const CUtensorMapDataType F = CU_TENSOR_MAP_DATA_TYPE_FLOAT32;

    CUtensorMap tmXT_A, tmXT_B, tmWQK, tmWV, tmQKa, tmQKb, tmV, tmATT;
    // xT [b][4096][512] fp16
    build_tm(enc, &tmXT_A, pxT, H, CC, NN, BB, (uint64_t)CC * 2, (uint64_t)NN * CC * 2, 64, 256);
    build_tm(enc, &tmXT_B, pxT, H, CC, NN, BB, (uint64_t)CC * 2, (uint64_t)NN * CC * 2, 64, 128);
    // wqk [128][512] fp16 as B
    build_tm(enc, &tmWQK, pwqk, H, CC, QK, 1, (uint64_t)CC * 2, (uint64_t)QK * CC * 2, 64, 128);
    // wr [512][512] fp16 as A
    build_tm(enc, &tmWV, pwr, H, CC, CC, 1, (uint64_t)CC * 2, (uint64_t)CC * CC * 2, 64, 256);
    // qk [b][4096][128] fp16: q half (koff 0) as A, k half (koff 64) as B
    build_tm(enc, &tmQKa, pqk, H, QK, NN, BB, (uint64_t)QK * 2, (uint64_t)NN * QK * 2, 64, 256);
    build_tm(enc, &tmQKb, pqk, H, QK, NN, BB, (uint64_t)QK * 2, (uint64_t)NN * QK * 2, 64, 128);
    // fp32: v [b][512][4096] as A, e [b][4096][4096] as B
    build_tm(enc, &tmV,   pv,   F, NN, CC, BB, (uint64_t)NN * 4, (uint64_t)CC * NN * 4, 32, 256);
    build_tm(enc, &tmATT, patt, F, NN, NN, BB, (uint64_t)NN * 4, (uint64_t)NN * NN * 4, 32, 128);

    cudaFuncSetAttribute(gemm16_kernel, cudaFuncAttributeMaxDynamicSharedMemorySize, G16_DSMEM);
    cudaFuncSetAttribute(av_kernel, cudaFuncAttributeMaxDynamicSharedMemorySize, G32_DSMEM);

    float* frs = (float*)prs;

    // 1. prep
    xT_half_kernel<<<dim3(NN / 32, CC / 32, BB), 256>>>(x);
    w_half_kernel<<<(CC * CC) / 256, 256>>>(Wv);
    wqk_prep_kernel<<<(QK * CC) / 256, 256>>>(Wq, bq, Wk, bk);
    // 2. qk projection (fp16): g_qkh[n][d] = xT·wqk^T + bqk[d], K=512
    gemm16_kernel<<<dim3(QK / BN, NN / BM, BB), 544, G16_DSMEM>>>(
        tmXT_A, tmWQK, CC, 3, 1, 0, 0, 0, (const float*)pbqk, frs,
        pqk, (size_t)NN * QK, QK);
    // 3. v projection (fp16 in, tf32 fp32 out): g_v[c][n] = wr·xT^T + bv[c], K=512
    gemm16_kernel<<<dim3(NN / BN, CC / BM, BB), 544, G16_DSMEM>>>(
        tmWV, tmXT_B, CC, 0, 0, 1, 0, 0, bv, frs,
        pv, (size_t)CC * NN, NN);
    // 4. scores + exp + rowsum (fp16): g_att[i][j] = tf32(exp(q·k)), K=64
    gemm16_kernel<<<dim3(NN / BN, NN / BM, BB), 544, G16_DSMEM>>>(
        tmQKa, tmQKb, DD, 2, 1, 1, 0, DD, nullptr, frs,
        patt, (size_t)NN * NN, NN);
    // 5. AV + normalize + epilogue (tf32): out = gamma*(v·e^T)/rs + x, K=4096
    av_kernel<<<dim3(CC / BM, NN / BN, BB), 544, G32_DSMEM>>>(
        tmV, tmATT, x, frs, gamma, out);
}

// round 9
// speedup vs baseline: 1.5360x; 1.2625x over previous
#include <cuda_runtime.h>
#include <cuda.h>
#include <cuda_fp16.h>
#include <cstdint>
#include <math.h>

constexpr int BB = 2;
constexpr int CC = 512;
constexpr int NN = 4096;
constexpr int DD = 64;
constexpr int QK = 128;

// ---------------------------------------------------------------------------
// Scratch
// ---------------------------------------------------------------------------
__device__ __align__(1024) __half   g_qkh[(size_t)BB * NN * QK];  // [b][n][q|k]
__device__ __align__(1024) __half   g_vh [(size_t)BB * CC * NN];  // [b][c][j]
__device__ __align__(1024) __half   g_xTh[(size_t)BB * NN * CC];  // [b][n][c]
__device__ __align__(1024) __half   g_wrh[(size_t)CC * CC];       // Wv
__device__ __align__(1024) __half   g_wqkh[(size_t)QK * CC];      // Wq|Wk
__device__ __align__(1024) float    g_bqk[QK];
__device__ __align__(1024) __half   g_eh [(size_t)BB * NN * NN];  // exp(s - m) fp16
__device__ __align__(1024) float    g_rs [(size_t)BB * NN];       // fp32 row sums
__device__ __align__(1024) unsigned g_rm [(size_t)BB * NN];       // encoded row max

// ---------------------------------------------------------------------------
// Helpers
// ---------------------------------------------------------------------------
__device__ __forceinline__ uint32_t smem_to_u32(const void* p) {
    uint32_t a;
    asm("{ .reg .u64 t; cvta.to.shared.u64 t, %1; cvt.u32.u64 %0, t; }"
        : "=r"(a) : "l"(p));
    return a;
}
// monotone float<->uint encoding for atomicMax
__device__ __forceinline__ unsigned fenc(float f) {
    unsigned u = __float_as_uint(f);
    return (u & 0x80000000u) ? ~u : (u | 0x80000000u);
}
__device__ __forceinline__ float fdec(unsigned e) {
    return (e & 0x80000000u) ? __uint_as_float(e ^ 0x80000000u)
                             : __uint_as_float(~e);
}

#define MBARRIER_INIT(addr, cnt) \
    asm volatile("mbarrier.init.shared.b64 [%0], %1;" \
        :: "r"((uint32_t)(addr)), "r"((uint32_t)(cnt)) : "memory")
#define MBARRIER_EXPECT_TX(addr, bytes) \
    asm volatile("mbarrier.arrive.expect_tx.shared.b64 _, [%0], %1;" \
        :: "r"((uint32_t)(addr)), "r"((uint32_t)(bytes)) : "memory")
#define MBARRIER_ARRIVE(addr) \
    asm volatile("mbarrier.arrive.shared.b64 _, [%0];" \
        :: "r"((uint32_t)(addr)) : "memory")
#define MBARRIER_WAIT_PARITY(addr, parity) do { \
    uint32_t _m = (uint32_t)(addr); uint32_t _p = (uint32_t)(parity); uint32_t _d; \
    asm volatile("{\n\t.reg .pred p;\n\t" \
        "mbarrier.try_wait.parity.shared.b64 p, [%1], %2;\n\t" \
        "selp.b32 %0, 1, 0, p;\n\t}" : "=r"(_d) : "r"(_m), "r"(_p) : "memory"); \
    if (!_d) { \
        asm volatile("{\n\t.reg .pred P1;\n\tWL_%=:\n\t" \
            "mbarrier.try_wait.parity.shared.b64 P1, [%0], %1, 0x989680;\n\t" \
            "@P1 bra.uni WD_%=;\n\tbra.uni WL_%=;\n\tWD_%=:\n\t}" \
            :: "r"(_m), "r"(_p) : "memory"); \
    } } while (0)

#define TMA_LOAD_3D(smem_addr, tmap, cx, cy, cz, mbar) \
    asm volatile( \
        "cp.async.bulk.tensor.3d.shared::cta.global.tile.mbarrier::complete_tx::bytes " \
        "[%0], [%1, {%2, %3, %4}], [%5];" \
        :: "r"((uint32_t)(smem_addr)), "l"(tmap), \
           "r"((int32_t)(cx)), "r"((int32_t)(cy)), "r"((int32_t)(cz)), \
           "r"((uint32_t)(mbar)) : "memory")

#define LDSM_X4(r0, r1, r2, r3, addr) \
    asm volatile("ldmatrix.sync.aligned.m8n8.x4.shared.b16 {%0,%1,%2,%3}, [%4];" \
        : "=r"(r0), "=r"(r1), "=r"(r2), "=r"(r3) : "r"(addr))

__device__ __forceinline__ void mma_f16(float* d, const uint32_t* a, const uint32_t* b) {
    asm volatile(
        "mma.sync.aligned.m16n8k16.row.col.f32.f16.f16.f32 "
        "{%0,%1,%2,%3}, {%4,%5,%6,%7}, {%8,%9}, {%0,%1,%2,%3};"
        : "+f"(d[0]), "+f"(d[1]), "+f"(d[2]), "+f"(d[3])
        : "r"(a[0]), "r"(a[1]), "r"(a[2]), "r"(a[3]), "r"(b[0]), "r"(b[1]));
}

// ---------------------------------------------------------------------------
// Prep kernels
// ---------------------------------------------------------------------------
__global__ __launch_bounds__(256) void xT_half_kernel(const float* __restrict__ x)
{
    __shared__ float t[32][33];
    const int b  = blockIdx.z;
    const int n0 = blockIdx.x * 32, c0 = blockIdx.y * 32;
    const int tx = threadIdx.x & 31, ty = threadIdx.x >> 5;
    const float* xb = x + (size_t)b * CC * NN;
    #pragma unroll
    for (int i = 0; i < 32; i += 8)
        t[ty + i][tx] = xb[(size_t)(c0 + ty + i) * NN + n0 + tx];
    __syncthreads();
    __half* o = g_xTh + (size_t)b * NN * CC;
    #pragma unroll
    for (int i = 0; i < 32; i += 8)
        o[(size_t)(n0 + ty + i) * CC + c0 + tx] = __float2half_rn(t[tx][ty + i]);
}

__global__ __launch_bounds__(256) void w_half_kernel(const float* __restrict__ W)
{
    int i = blockIdx.x * 256 + threadIdx.x;
    g_wrh[i] = __float2half_rn(W[i]);
}

__global__ __launch_bounds__(256) void wqk_prep_kernel(
    const float* __restrict__ Wq, const float* __restrict__ bq,
    const float* __restrict__ Wk, const float* __restrict__ bk)
{
    int i = blockIdx.x * 256 + threadIdx.x;     // 65536 threads
    int r = i >> 9, c = i & 511;
    g_wqkh[i] = __float2half_rn(r < DD ? Wq[(size_t)r * CC + c]
                                       : Wk[(size_t)(r - DD) * CC + c]);
    if (i < QK) g_bqk[i] = (i < DD) ? bq[i] : bk[i - DD];
    if (i < BB * NN) { g_rs[i] = 0.0f; g_rm[i] = 0x007FFFFFu; }  // enc(-inf)
}

// ---------------------------------------------------------------------------
// fp16 GEMM: C[m][n] = sum_k A[m][k]*B[n][k], fp32 accum, tile 256x128, BK=64.
// mode 0: half out = C + bias[row]                    (v-proj)
// mode 2: half out = exp(C - rowmax); fp32 rowsum     (scores)
// mode 3: half out = C + bias[col]                    (qk-proj)
// mode 4: no out; atomicMax rowmax                    (max pass)
// ---------------------------------------------------------------------------
constexpr int BM = 256, BN = 128;
constexpr int NSTAGE = 3;
constexpr int A16_BY = BM * 128;
constexpr int B16_BY = BN * 128;
constexpr int STG16_BY = A16_BY + B16_BY;
constexpr int G16_DSMEM = NSTAGE * STG16_BY + 1024;

__global__ __launch_bounds__(544)
void gemm16_kernel(const __grid_constant__ CUtensorMap tma_a,
                   const __grid_constant__ CUtensorMap tma_b,
                   int k_total, int mode, int a_batched, int b_batched,
                   int a_koff, int b_koff,
                   const float* __restrict__ aux,
                   float* __restrict__ rs, unsigned* __restrict__ rm,
                   void* __restrict__ outp, size_t out_bstride, int out_rstride)
{
    __shared__ __align__(8) uint64_t s_bar[2 * NSTAGE];
    extern __shared__ char dsm[];
    const uint32_t dbase = (smem_to_u32(dsm) + 1023) & ~1023u;
    const uint32_t sbar  = smem_to_u32(s_bar);

    const int tid = threadIdx.x, wid = tid >> 5, lid = tid & 31;
    const int mBase = blockIdx.y * BM;
    const int nBase = blockIdx.x * BN;
    const int b     = blockIdx.z;
    const int nchunk = k_total / 64;

    if (tid == 0) {
        #pragma unroll
        for (int s = 0; s < NSTAGE; s++) {
            MBARRIER_INIT(sbar + s * 16, 1);
            MBARRIER_INIT(sbar + s * 16 + 8, 16);
        }
    }
    __syncthreads();

    if (tid == 512) {
        const int az = a_batched ? b : 0;
        const int bz = b_batched ? b : 0;
        int ph = 1, st = 0;
        for (int c = 0; c < nchunk; c++) {
            MBARRIER_WAIT_PARITY(sbar + st * 16 + 8, ph);
            MBARRIER_EXPECT_TX(sbar + st * 16, STG16_BY);
            TMA_LOAD_3D(dbase + st * STG16_BY,          &tma_a, a_koff + c * 64, mBase, az, sbar + st * 16);
            TMA_LOAD_3D(dbase + st * STG16_BY + A16_BY, &tma_b, b_koff + c * 64, nBase, bz, sbar + st * 16);
            if (++st == NSTAGE) { st = 0; ph ^= 1; }
        }
    }

    if (wid < 16) {
        const int wm = wid & 3, wn = wid >> 2;
        const int mWarp = wm * 64, nWarp = wn * 32;
        const int laneA = lid & 15;
        const int hAu   = (lid >> 4) & 1;
        const int laneB = (lid & 7) + ((lid & 16) ? 8 : 0);
        const int hBu   = (lid >> 3) & 1;
        const int xor7  = lid & 7;

        float cacc[4][4][4] = {};

        int ph = 0, st = 0;
        for (int c = 0; c < nchunk; c++) {
            MBARRIER_WAIT_PARITY(sbar + st * 16, ph);
            const uint32_t Ab = dbase + st * STG16_BY;
            const uint32_t Bb = Ab + A16_BY;
            const uint32_t aRowAddr = Ab + (mWarp + laneA) * 128;
            const uint32_t bRowAddr = Bb + (nWarp + laneB) * 128;

            #pragma unroll
            for (int ks = 0; ks < 4; ks++) {
                uint32_t af[4][4];
                uint32_t bf[4][2];
                const uint32_t cA = (uint32_t)(((2 * ks + hAu) ^ xor7) << 4);
                const uint32_t cB = (uint32_t)(((2 * ks + hBu) ^ xor7) << 4);
                #pragma unroll
                for (int mt = 0; mt < 4; mt++)
                    LDSM_X4(af[mt][0], af[mt][1], af[mt][2], af[mt][3],
                            aRowAddr + mt * (16 * 128) + cA);
                #pragma unroll
                for (int p = 0; p < 2; p++) {
                    uint32_t r0, r1, r2, r3;
                    LDSM_X4(r0, r1, r2, r3, bRowAddr + p * (16 * 128) + cB);
                    bf[2*p][0] = r0; bf[2*p][1] = r1;
                    bf[2*p+1][0] = r2; bf[2*p+1][1] = r3;
                }
                #pragma unroll
                for (int mt = 0; mt < 4; mt++)
                    #pragma unroll
                    for (int nt = 0; nt < 4; nt++)
                        mma_f16(cacc[mt][nt], af[mt], bf[nt]);
            }
            if (lid == 0) MBARRIER_ARRIVE(sbar + st * 16 + 8);
            if (++st == NSTAGE) { st = 0; ph ^= 1; }
        }

        // ---- epilogue ----
        const int g = lid >> 2, t4 = lid & 3;
        float* rs_b = rs + (size_t)b * NN;
        unsigned* rm_b = rm + (size_t)b * NN;

        #pragma unroll
        for (int mt = 0; mt < 4; mt++) {
            const int r0 = mBase + mWarp + mt * 16 + g;
            const int r1 = r0 + 8;

            if (mode == 4) {
                float m0 = -1e30f, m1 = -1e30f;
                #pragma unroll
                for (int nt = 0; nt < 4; nt++) {
                    m0 = fmaxf(m0, fmaxf(cacc[mt][nt][0], cacc[mt][nt][1]));
                    m1 = fmaxf(m1, fmaxf(cacc[mt][nt][2], cacc[mt][nt][3]));
                }
                m0 = fmaxf(m0, __shfl_xor_sync(~0u, m0, 1));
                m0 = fmaxf(m0, __shfl_xor_sync(~0u, m0, 2));
                m1 = fmaxf(m1, __shfl_xor_sync(~0u, m1, 1));
                m1 = fmaxf(m1, __shfl_xor_sync(~0u, m1, 2));
                if (t4 == 0) {
                    atomicMax(&rm_b[r0], fenc(m0));
                    atomicMax(&rm_b[r1], fenc(m1));
                }
                continue;
            }

            __half* ob = (__half*)outp + (size_t)b * out_bstride;
            float bias0 = 0.f, bias1 = 0.f;
            if (mode == 0) { bias0 = aux[r0]; bias1 = aux[r1]; }
            float m0 = 0.f, m1 = 0.f;
            if (mode == 2) { m0 = fdec(rm_b[r0]); m1 = fdec(rm_b[r1]); }
            float s0 = 0.f, s1 = 0.f;
            #pragma unroll
            for (int nt = 0; nt < 4; nt++) {
                const int col = nBase + nWarp + nt * 8 + t4 * 2;
                float v00 = cacc[mt][nt][0], v01 = cacc[mt][nt][1];
                float v10 = cacc[mt][nt][2], v11 = cacc[mt][nt][3];
                if (mode == 3) {
                    const float bc0 = aux[col], bc1 = aux[col + 1];
                    v00 += bc0; v01 += bc1; v10 += bc0; v11 += bc1;
                } else if (mode == 0) {
                    v00 += bias0; v01 += bias0; v10 += bias1; v11 += bias1;
                } else {    // mode 2
                    v00 = __expf(v00 - m0); v01 = __expf(v01 - m0);
                    v10 = __expf(v10 - m1); v11 = __expf(v11 - m1);
                    s0 += v00 + v01; s1 += v10 + v11;
                }
                *(__half2*)&ob[(size_t)r0 * out_rstride + col] = __floats2half2_rn(v00, v01);
                *(__half2*)&ob[(size_t)r1 * out_rstride + col] = __floats2half2_rn(v10, v11);
            }
            if (mode == 2) {
                s0 += __shfl_xor_sync(0xFFFFFFFFu, s0, 1);
                s0 += __shfl_xor_sync(0xFFFFFFFFu, s0, 2);
                s1 += __shfl_xor_sync(0xFFFFFFFFu, s1, 1);
                s1 += __shfl_xor_sync(0xFFFFFFFFu, s1, 2);
                if (t4 == 0) {
                    atomicAdd(&rs_b[r0], s0);
                    atomicAdd(&rs_b[r1], s1);
                }
            }
        }
    }
}

// ---------------------------------------------------------------------------
// fp16 AV GEMM: out[c][i] = gamma * (sum_j v[c][j]*e[i][j]) / rs[i] + x[c][i]
// Tile 256(c) x 128(i) x 64(j). Grid: (c-tiles, i-tiles, b).
// ---------------------------------------------------------------------------
__global__ __launch_bounds__(544)
void av16_kernel(const __grid_constant__ CUtensorMap tma_v,
                 const __grid_constant__ CUtensorMap tma_e,
                 const float* __restrict__ x,
                 const float* __restrict__ rs,
                 const float* __restrict__ gamma,
                 float* __restrict__ outp)
{
    __shared__ __align__(8) uint64_t s_bar[2 * NSTAGE];
    extern __shared__ char dsm[];
    const uint32_t dbase = (smem_to_u32(dsm) + 1023) & ~1023u;
    const uint32_t sbar  = smem_to_u32(s_bar);

    const int tid = threadIdx.x, wid = tid >> 5, lid = tid & 31;
    const int mBase = blockIdx.x * BM;      // c
    const int nBase = blockIdx.y * BN;      // i
    const int b     = blockIdx.z;
    const int nchunk = NN / 64;

    if (tid == 0) {
        #pragma unroll
        for (int s = 0; s < NSTAGE; s++) {
            MBARRIER_INIT(sbar + s * 16, 1);
            MBARRIER_INIT(sbar + s * 16 + 8, 16);
        }
    }
    __syncthreads();

    if (tid == 512) {
        int ph = 1, st = 0;
        for (int c = 0; c < nchunk; c++) {
            MBARRIER_WAIT_PARITY(sbar + st * 16 + 8, ph);
            MBARRIER_EXPECT_TX(sbar + st * 16, STG16_BY);
            TMA_LOAD_3D(dbase + st * STG16_BY,          &tma_v, c * 64, mBase, b, sbar + st * 16);
            TMA_LOAD_3D(dbase + st * STG16_BY + A16_BY, &tma_e, c * 64, nBase, b, sbar + st * 16);
            if (++st == NSTAGE) { st = 0; ph ^= 1; }
        }
    }

    if (wid < 16) {
        const int wm = wid & 3, wn = wid >> 2;
        const int mWarp = wm * 64, nWarp = wn * 32;
        const int laneA = lid & 15;
        const int hAu   = (lid >> 4) & 1;
        const int laneB = (lid & 7) + ((lid & 16) ? 8 : 0);
        const int hBu   = (lid >> 3) & 1;
        const int xor7  = lid & 7;

        float cacc[4][4][4] = {};

        int ph = 0, st = 0;
        for (int c = 0; c < nchunk; c++) {
            MBARRIER_WAIT_PARITY(sbar + st * 16, ph);
            const uint32_t Ab = dbase + st * STG16_BY;
            const uint32_t Bb = Ab + A16_BY;
            const uint32_t aRowAddr = Ab + (mWarp + laneA) * 128;
            const uint32_t bRowAddr = Bb + (nWarp + laneB) * 128;

            #pragma unroll
            for (int ks = 0; ks < 4; ks++) {
                uint32_t af[4][4];
                uint32_t bf[4][2];
                const uint32_t cA = (uint32_t)(((2 * ks + hAu) ^ xor7) << 4);
                const uint32_t cB = (uint32_t)(((2 * ks + hBu) ^ xor7) << 4);
                #pragma unroll
                for (int mt = 0; mt < 4; mt++)
                    LDSM_X4(af[mt][0], af[mt][1], af[mt][2], af[mt][3],
                            aRowAddr + mt * (16 * 128) + cA);
                #pragma unroll
                for (int p = 0; p < 2; p++) {
                    uint32_t r0, r1, r2, r3;
                    LDSM_X4(r0, r1, r2, r3, bRowAddr + p * (16 * 128) + cB);
                    bf[2*p][0] = r0; bf[2*p][1] = r1;
                    bf[2*p+1][0] = r2; bf[2*p+1][1] = r3;
                }
                #pragma unroll
                for (int mt = 0; mt < 4; mt++)
                    #pragma unroll
                    for (int nt = 0; nt < 4; nt++)
                        mma_f16(cacc[mt][nt], af[mt], bf[nt]);
            }
            if (lid == 0) MBARRIER_ARRIVE(sbar + st * 16 + 8);
            if (++st == NSTAGE) { st = 0; ph ^= 1; }
        }

        const int g = lid >> 2, t4 = lid & 3;
        const float gm = gamma[0];
        const float* rs_b = rs + (size_t)b * NN;
        const float* xb = x + (size_t)b * CC * NN;
        float* ob = outp + (size_t)b * CC * NN;

        #pragma unroll
        for (int mt = 0; mt < 4; mt++) {
            const int r0 = mBase + mWarp + mt * 16 + g;
            const int r1 = r0 + 8;
            #pragma unroll
            for (int nt = 0; nt < 4; nt++) {
                const int col = nBase + nWarp + nt * 8 + t4 * 2;
                const float i0 = __fdividef(1.0f, rs_b[col]);
                const float i1 = __fdividef(1.0f, rs_b[col + 1]);
                const float2 x0 = *(const float2*)&xb[(size_t)r0 * NN + col];
                const float2 x1 = *(const float2*)&xb[(size_t)r1 * NN + col];
                *(float2*)&ob[(size_t)r0 * NN + col] =
                    make_float2(gm * cacc[mt][nt][0] * i0 + x0.x,
                                gm * cacc[mt][nt][1] * i1 + x0.y);
                *(float2*)&ob[(size_t)r1 * NN + col] =
                    make_float2(gm * cacc[mt][nt][2] * i0 + x1.x,
                                gm * cacc[mt][nt][3] * i1 + x1.y);
            }
        }
    }
}

// ---------------------------------------------------------------------------
// Host side
// ---------------------------------------------------------------------------
typedef CUresult (*EncodeFn)(CUtensorMap*, CUtensorMapDataType, cuuint32_t, void*,
                             const cuuint64_t*, const cuuint64_t*, const cuuint32_t*,
                             const cuuint32_t*, CUtensorMapInterleave, CUtensorMapSwizzle,
                             CUtensorMapL2promotion, CUtensorMapFloatOOBfill);

static void build_tm(EncodeFn enc, CUtensorMap* tm, void* ptr,
                     uint64_t d0, uint64_t d1, uint64_t d2,
                     uint64_t s1b, uint64_t s2b, uint32_t b0, uint32_t b1)
{
    cuuint64_t dims[3] = {d0, d1, d2};
    cuuint64_t str[2]  = {s1b, s2b};
    cuuint32_t box[3]  = {b0, b1, 1};
    cuuint32_t es[3]   = {1, 1, 1};
    enc(tm, CU_TENSOR_MAP_DATA_TYPE_FLOAT16, 3, ptr, dims, str, box, es,
        CU_TENSOR_MAP_INTERLEAVE_NONE, CU_TENSOR_MAP_SWIZZLE_128B,
        CU_TENSOR_MAP_L2_PROMOTION_L2_128B, CU_TENSOR_MAP_FLOAT_OOB_FILL_NONE);
}

extern "C" void kernel_launch(void* const* d_in, const int* in_sizes, int n_in,
                              void* d_out, int out_size)
{
    (void)in_sizes; (void)n_in; (void)out_size;
    const float* x     = (const float*)d_in[0];
    const float* Wq    = (const float*)d_in[1];
    const float* bq    = (const float*)d_in[2];
    const float* Wk    = (const float*)d_in[3];
    const float* bk    = (const float*)d_in[4];
    const float* Wv    = (const float*)d_in[5];
    const float* bv    = (const float*)d_in[6];
    const float* gamma = (const float*)d_in[7];
    float* out = (float*)d_out;

    EncodeFn enc = nullptr;
    cudaDriverEntryPointQueryResult qr;
    cudaGetDriverEntryPointByVersion("cuTensorMapEncodeTiled", (void**)&enc, 12000,
                                     cudaEnableDefault, &qr);

    void *pqk, *pvh, *peh, *pxT, *pwr, *pwqk, *pbqk, *prs, *prm;
    cudaGetSymbolAddress(&pqk,  g_qkh);
    cudaGetSymbolAddress(&pvh,  g_vh);
    cudaGetSymbolAddress(&peh,  g_eh);
    cudaGetSymbolAddress(&pxT,  g_xTh);
    cudaGetSymbolAddress(&pwr,  g_wrh);
    cudaGetSymbolAddress(&pwqk, g_wqkh);
    cudaGetSymbolAddress(&pbqk, g_bqk);
    cudaGetSymbolAddress(&prs,  g_rs);
    cudaGetSymbolAddress(&prm,  g_rm);

    CUtensorMap tmXT_A, tmXT_B, tmWQK, tmWV, tmQKa, tmQKb, tmVh, tmEh;
    build_tm(enc, &tmXT_A, pxT, CC, NN, BB, (uint64_t)CC * 2, (uint64_t)NN * CC * 2, 64, 256);
    build_tm(enc, &tmXT_B, pxT, CC, NN, BB, (uint64_t)CC * 2, (uint64_t)NN * CC * 2, 64, 128);
    build_tm(enc, &tmWQK, pwqk, CC, QK, 1, (uint64_t)CC * 2, (uint64_t)QK * CC * 2, 64, 128);
    build_tm(enc, &tmWV, pwr, CC, CC, 1, (uint64_t)CC * 2, (uint64_t)CC * CC * 2, 64, 256);
    build_tm(enc, &tmQKa, pqk, QK, NN, BB, (uint64_t)QK * 2, (uint64_t)NN * QK * 2, 64, 256);
    build_tm(enc, &tmQKb, pqk, QK, NN, BB, (uint64_t)QK * 2, (uint64_t)NN * QK * 2, 64, 128);
    build_tm(enc, &tmVh, pvh, NN, CC, BB, (uint64_t)NN * 2, (uint64_t)CC * NN * 2, 64, 256);
    build_tm(enc, &tmEh, peh, NN, NN, BB, (uint64_t)NN * 2, (uint64_t)NN * NN * 2, 64, 128);

    cudaFuncSetAttribute(gemm16_kernel, cudaFuncAttributeMaxDynamicSharedMemorySize, G16_DSMEM);
    cudaFuncSetAttribute(av16_kernel, cudaFuncAttributeMaxDynamicSharedMemorySize, G16_DSMEM);

    float* frs = (float*)prs;
    unsigned* frm = (unsigned*)prm;

    // 1. prep (also zeroes rs, inits rm)
    xT_half_kernel<<<dim3(NN / 32, CC / 32, BB), 256>>>(x);
    w_half_kernel<<<(CC * CC) / 256, 256>>>(Wv);
    wqk_prep_kernel<<<(QK * CC) / 256, 256>>>(Wq, bq, Wk, bk);
    // 2. qk projection: g_qkh[n][d] = xT·wqk^T + bqk[d], K=512
    gemm16_kernel<<<dim3(QK / BN, NN / BM, BB), 544, G16_DSMEM>>>(
        tmXT_A, tmWQK, CC, 3, 1, 0, 0, 0, (const float*)pbqk, frs, frm,
        pqk, (size_t)NN * QK, QK);
    // 3. v projection: g_vh[c][n] = wr·xT^T + bv[c], K=512
    gemm16_kernel<<<dim3(NN / BN, CC / BM, BB), 544, G16_DSMEM>>>(
        tmWV, tmXT_B, CC, 0, 0, 1, 0, 0, bv, frs, frm,
        pvh, (size_t)CC * NN, NN);
    // 4. row max pass: rm[i] = max_j q_i·k_j, K=64 (no tile output)
    gemm16_kernel<<<dim3(NN / BN, NN / BM, BB), 544, G16_DSMEM>>>(
        tmQKa, tmQKb, DD, 4, 1, 1, 0, DD, nullptr, frs, frm,
        nullptr, 0, 0);
    // 5. scores: g_eh[i][j] = fp16(exp(q·k - rm[i])), rowsums fp32, K=64
    gemm16_kernel<<<dim3(NN / BN, NN / BM, BB), 544, G16_DSMEM>>>(
        tmQKa, tmQKb, DD, 2, 1, 1, 0, DD, nullptr, frs, frm,
        peh, (size_t)NN * NN, NN);
    // 6. AV (fp16): out = gamma*(v·e^T)/rs + x, K=4096
    av16_kernel<<<dim3(CC / BM, NN / BN, BB), 544, G16_DSMEM>>>(
        tmVh, tmEh, x, frs, gamma, out);
}

// round 10
// speedup vs baseline: 1.5850x; 1.0319x over previous
#include <cuda_runtime.h>
#include <cuda.h>
#include <cuda_fp16.h>
#include <cstdint>
#include <math.h>

constexpr int BB = 2;
constexpr int CC = 512;
constexpr int NN = 4096;
constexpr int DD = 64;
constexpr int QK = 128;

// ---------------------------------------------------------------------------
// Scratch
// ---------------------------------------------------------------------------
__device__ __align__(1024) __half   g_qkh[(size_t)BB * NN * QK];  // [b][n][q|k]
__device__ __align__(1024) __half   g_vh [(size_t)BB * CC * NN];  // [b][c][j]
__device__ __align__(1024) __half   g_xTh[(size_t)BB * NN * CC];  // [b][n][c]
__device__ __align__(1024) __half   g_wrh[(size_t)CC * CC];       // Wv
__device__ __align__(1024) __half   g_wqkh[(size_t)QK * CC];      // Wq|Wk
__device__ __align__(1024) float    g_bqk[QK];
__device__ __align__(1024) __half   g_eh [(size_t)BB * NN * NN];  // exp(s - m)
__device__ __align__(1024) float    g_rs [(size_t)BB * NN];       // fp32 row sums
__device__ __align__(1024) unsigned g_rm [(size_t)BB * NN];       // encoded row max

// ---------------------------------------------------------------------------
// Helpers
// ---------------------------------------------------------------------------
__device__ __forceinline__ uint32_t smem_to_u32(const void* p) {
    uint32_t a;
    asm("{ .reg .u64 t; cvta.to.shared.u64 t, %1; cvt.u32.u64 %0, t; }"
        : "=r"(a) : "l"(p));
    return a;
}
__device__ __forceinline__ unsigned fenc(float f) {
    unsigned u = __float_as_uint(f);
    return (u & 0x80000000u) ? ~u : (u | 0x80000000u);
}
__device__ __forceinline__ float fdec(unsigned e) {
    return (e & 0x80000000u) ? __uint_as_float(e ^ 0x80000000u)
                             : __uint_as_float(~e);
}

#define MBARRIER_INIT(addr, cnt) \
    asm volatile("mbarrier.init.shared.b64 [%0], %1;" \
        :: "r"((uint32_t)(addr)), "r"((uint32_t)(cnt)) : "memory")
#define MBARRIER_EXPECT_TX(addr, bytes) \
    asm volatile("mbarrier.arrive.expect_tx.shared.b64 _, [%0], %1;" \
        :: "r"((uint32_t)(addr)), "r"((uint32_t)(bytes)) : "memory")
#define MBARRIER_ARRIVE(addr) \
    asm volatile("mbarrier.arrive.shared.b64 _, [%0];" \
        :: "r"((uint32_t)(addr)) : "memory")
#define MBARRIER_WAIT_PARITY(addr, parity) do { \
    uint32_t _m = (uint32_t)(addr); uint32_t _p = (uint32_t)(parity); uint32_t _d; \
    asm volatile("{\n\t.reg .pred p;\n\t" \
        "mbarrier.try_wait.parity.shared.b64 p, [%1], %2;\n\t" \
        "selp.b32 %0, 1, 0, p;\n\t}" : "=r"(_d) : "r"(_m), "r"(_p) : "memory"); \
    if (!_d) { \
        asm volatile("{\n\t.reg .pred P1;\n\tWL_%=:\n\t" \
            "mbarrier.try_wait.parity.shared.b64 P1, [%0], %1, 0x989680;\n\t" \
            "@P1 bra.uni WD_%=;\n\tbra.uni WL_%=;\n\tWD_%=:\n\t}" \
            :: "r"(_m), "r"(_p) : "memory"); \
    } } while (0)

#define TMA_LOAD_3D(smem_addr, tmap, cx, cy, cz, mbar) \
    asm volatile( \
        "cp.async.bulk.tensor.3d.shared::cta.global.tile.mbarrier::complete_tx::bytes " \
        "[%0], [%1, {%2, %3, %4}], [%5];" \
        :: "r"((uint32_t)(smem_addr)), "l"(tmap), \
           "r"((int32_t)(cx)), "r"((int32_t)(cy)), "r"((int32_t)(cz)), \
           "r"((uint32_t)(mbar)) : "memory")

#define LDSM_X4(r0, r1, r2, r3, addr) \
    asm volatile("ldmatrix.sync.aligned.m8n8.x4.shared.b16 {%0,%1,%2,%3}, [%4];" \
        : "=r"(r0), "=r"(r1), "=r"(r2), "=r"(r3) : "r"(addr))

__device__ __forceinline__ void mma_f16(float* d, const uint32_t* a, const uint32_t* b) {
    asm volatile(
        "mma.sync.aligned.m16n8k16.row.col.f32.f16.f16.f32 "
        "{%0,%1,%2,%3}, {%4,%5,%6,%7}, {%8,%9}, {%0,%1,%2,%3};"
        : "+f"(d[0]), "+f"(d[1]), "+f"(d[2]), "+f"(d[3])
        : "r"(a[0]), "r"(a[1]), "r"(a[2]), "r"(a[3]), "r"(b[0]), "r"(b[1]));
}

// ---------------------------------------------------------------------------
// Prep kernels
// ---------------------------------------------------------------------------
__global__ __launch_bounds__(256) void xT_half_kernel(const float* __restrict__ x)
{
    __shared__ float t[32][33];
    const int b  = blockIdx.z;
    const int n0 = blockIdx.x * 32, c0 = blockIdx.y * 32;
    const int tx = threadIdx.x & 31, ty = threadIdx.x >> 5;
    const float* xb = x + (size_t)b * CC * NN;
    #pragma unroll
    for (int i = 0; i < 32; i += 8)
        t[ty + i][tx] = xb[(size_t)(c0 + ty + i) * NN + n0 + tx];
    __syncthreads();
    __half* o = g_xTh + (size_t)b * NN * CC;
    #pragma unroll
    for (int i = 0; i < 32; i += 8)
        o[(size_t)(n0 + ty + i) * CC + c0 + tx] = __float2half_rn(t[tx][ty + i]);
}

__global__ __launch_bounds__(256) void w_half_kernel(const float* __restrict__ W)
{
    int i = blockIdx.x * 256 + threadIdx.x;
    g_wrh[i] = __float2half_rn(W[i]);
}

__global__ __launch_bounds__(256) void wqk_prep_kernel(
    const float* __restrict__ Wq, const float* __restrict__ bq,
    const float* __restrict__ Wk, const float* __restrict__ bk)
{
    int i = blockIdx.x * 256 + threadIdx.x;
    int r = i >> 9, c = i & 511;
    g_wqkh[i] = __float2half_rn(r < DD ? Wq[(size_t)r * CC + c]
                                       : Wk[(size_t)(r - DD) * CC + c]);
    if (i < QK) g_bqk[i] = (i < DD) ? bq[i] : bk[i - DD];
    if (i < BB * NN) { g_rs[i] = 0.0f; g_rm[i] = 0x007FFFFFu; }
}

// ---------------------------------------------------------------------------
// fp16 GEMM, templated on MT (warp m-tiles): BM = MT*64, BN = 128, BK = 64.
// mode 0: half out = C + bias[row]                    (v-proj)
// mode 2: half out = exp(C - rowmax); fp32 rowsum     (scores)
// mode 3: half out = C + bias[col]                    (qk-proj)
// mode 4: no out; atomicMax rowmax                    (max pass)
// ---------------------------------------------------------------------------
constexpr int BN = 128;
constexpr int NSTAGE = 3;
constexpr int B16_BY = BN * 128;                  // 16 KB

template<int MT>
__global__ __launch_bounds__(544)
void gemm16_kernel(const __grid_constant__ CUtensorMap tma_a,
                   const __grid_constant__ CUtensorMap tma_b,
                   int k_total, int mode, int a_batched, int b_batched,
                   int a_koff, int b_koff,
                   const float* __restrict__ aux,
                   float* __restrict__ rs, unsigned* __restrict__ rm,
                   void* __restrict__ outp, size_t out_bstride, int out_rstride)
{
    constexpr int BM_T = MT * 64;
    constexpr int A_BY = BM_T * 128;
    constexpr int STG  = A_BY + B16_BY;

    __shared__ __align__(8) uint64_t s_bar[2 * NSTAGE];
    extern __shared__ char dsm[];
    const uint32_t dbase = (smem_to_u32(dsm) + 1023) & ~1023u;
    const uint32_t sbar  = smem_to_u32(s_bar);

    const int tid = threadIdx.x, wid = tid >> 5, lid = tid & 31;
    const int mBase = blockIdx.y * BM_T;
    const int nBase = blockIdx.x * BN;
    const int b     = blockIdx.z;
    const int nchunk = k_total / 64;

    if (tid == 0) {
        #pragma unroll
        for (int s = 0; s < NSTAGE; s++) {
            MBARRIER_INIT(sbar + s * 16, 1);
            MBARRIER_INIT(sbar + s * 16 + 8, 16);
        }
    }
    __syncthreads();

    if (tid == 512) {
        const int az = a_batched ? b : 0;
        const int bz = b_batched ? b : 0;
        int ph = 1, st = 0;
        for (int c = 0; c < nchunk; c++) {
            MBARRIER_WAIT_PARITY(sbar + st * 16 + 8, ph);
            MBARRIER_EXPECT_TX(sbar + st * 16, STG);
            TMA_LOAD_3D(dbase + st * STG,        &tma_a, a_koff + c * 64, mBase, az, sbar + st * 16);
            TMA_LOAD_3D(dbase + st * STG + A_BY, &tma_b, b_koff + c * 64, nBase, bz, sbar + st * 16);
            if (++st == NSTAGE) { st = 0; ph ^= 1; }
        }
    }

    if (wid < 16) {
        const int wm = wid & 3, wn = wid >> 2;
        const int mWarp = wm * (MT * 16), nWarp = wn * 32;
        const int laneA = lid & 15;
        const int hAu   = (lid >> 4) & 1;
        const int laneB = (lid & 7) + ((lid & 16) ? 8 : 0);
        const int hBu   = (lid >> 3) & 1;
        const int xor7  = lid & 7;

        float cacc[MT][4][4] = {};

        int ph = 0, st = 0;
        for (int c = 0; c < nchunk; c++) {
            MBARRIER_WAIT_PARITY(sbar + st * 16, ph);
            const uint32_t Ab = dbase + st * STG;
            const uint32_t Bb = Ab + A_BY;
            const uint32_t aRowAddr = Ab + (mWarp + laneA) * 128;
            const uint32_t bRowAddr = Bb + (nWarp + laneB) * 128;

            #pragma unroll
            for (int ks = 0; ks < 4; ks++) {
                uint32_t af[MT][4];
                uint32_t bf[4][2];
                const uint32_t cA = (uint32_t)(((2 * ks + hAu) ^ xor7) << 4);
                const uint32_t cB = (uint32_t)(((2 * ks + hBu) ^ xor7) << 4);
                #pragma unroll
                for (int mt = 0; mt < MT; mt++)
                    LDSM_X4(af[mt][0], af[mt][1], af[mt][2], af[mt][3],
                            aRowAddr + mt * (16 * 128) + cA);
                #pragma unroll
                for (int p = 0; p < 2; p++) {
                    uint32_t r0, r1, r2, r3;
                    LDSM_X4(r0, r1, r2, r3, bRowAddr + p * (16 * 128) + cB);
                    bf[2*p][0] = r0; bf[2*p][1] = r1;
                    bf[2*p+1][0] = r2; bf[2*p+1][1] = r3;
                }
                #pragma unroll
                for (int mt = 0; mt < MT; mt++)
                    #pragma unroll
                    for (int nt = 0; nt < 4; nt++)
                        mma_f16(cacc[mt][nt], af[mt], bf[nt]);
            }
            if (lid == 0) MBARRIER_ARRIVE(sbar + st * 16 + 8);
            if (++st == NSTAGE) { st = 0; ph ^= 1; }
        }

        // ---- epilogue ----
        const int g = lid >> 2, t4 = lid & 3;
        float* rs_b = rs + (size_t)b * NN;
        unsigned* rm_b = rm + (size_t)b * NN;

        #pragma unroll
        for (int mt = 0; mt < MT; mt++) {
            const int r0 = mBase + mWarp + mt * 16 + g;
            const int r1 = r0 + 8;

            if (mode == 4) {
                float m0 = -1e30f, m1 = -1e30f;
                #pragma unroll
                for (int nt = 0; nt < 4; nt++) {
                    m0 = fmaxf(m0, fmaxf(cacc[mt][nt][0], cacc[mt][nt][1]));
                    m1 = fmaxf(m1, fmaxf(cacc[mt][nt][2], cacc[mt][nt][3]));
                }
                m0 = fmaxf(m0, __shfl_xor_sync(~0u, m0, 1));
                m0 = fmaxf(m0, __shfl_xor_sync(~0u, m0, 2));
                m1 = fmaxf(m1, __shfl_xor_sync(~0u, m1, 1));
                m1 = fmaxf(m1, __shfl_xor_sync(~0u, m1, 2));
                if (t4 == 0) {
                    atomicMax(&rm_b[r0], fenc(m0));
                    atomicMax(&rm_b[r1], fenc(m1));
                }
                continue;
            }

            __half* ob = (__half*)outp + (size_t)b * out_bstride;
            float bias0 = 0.f, bias1 = 0.f;
            if (mode == 0) { bias0 = aux[r0]; bias1 = aux[r1]; }
            float m0 = 0.f, m1 = 0.f;
            if (mode == 2) { m0 = fdec(rm_b[r0]); m1 = fdec(rm_b[r1]); }
            float s0 = 0.f, s1 = 0.f;
            #pragma unroll
            for (int nt = 0; nt < 4; nt++) {
                const int col = nBase + nWarp + nt * 8 + t4 * 2;
                float v00 = cacc[mt][nt][0], v01 = cacc[mt][nt][1];
                float v10 = cacc[mt][nt][2], v11 = cacc[mt][nt][3];
                if (mode == 3) {
                    const float bc0 = aux[col], bc1 = aux[col + 1];
                    v00 += bc0; v01 += bc1; v10 += bc0; v11 += bc1;
                } else if (mode == 0) {
                    v00 += bias0; v01 += bias0; v10 += bias1; v11 += bias1;
                } else {    // mode 2
                    v00 = __expf(v00 - m0); v01 = __expf(v01 - m0);
                    v10 = __expf(v10 - m1); v11 = __expf(v11 - m1);
                    s0 += v00 + v01; s1 += v10 + v11;
                }
                *(__half2*)&ob[(size_t)r0 * out_rstride + col] = __floats2half2_rn(v00, v01);
                *(__half2*)&ob[(size_t)r1 * out_rstride + col] = __floats2half2_rn(v10, v11);
            }
            if (mode == 2) {
                s0 += __shfl_xor_sync(0xFFFFFFFFu, s0, 1);
                s0 += __shfl_xor_sync(0xFFFFFFFFu, s0, 2);
                s1 += __shfl_xor_sync(0xFFFFFFFFu, s1, 1);
                s1 += __shfl_xor_sync(0xFFFFFFFFu, s1, 2);
                if (t4 == 0) {
                    atomicAdd(&rs_b[r0], s0);
                    atomicAdd(&rs_b[r1], s1);
                }
            }
        }
    }
}

// ---------------------------------------------------------------------------
// fp16 AV GEMM with BK=128: out[c][i] = gamma*(sum_j v[c][j]*e[i][j])/rs[i] + x
// Tile 256(c) x 128(i) x 128(j), 2 stages x 96 KB.
// ---------------------------------------------------------------------------
constexpr int AV_A_ST = 256 * 256;                // 64 KB (256 rows x 128 k x 2B)
constexpr int AV_B_ST = 128 * 256;                // 32 KB
constexpr int AV_STG  = AV_A_ST + AV_B_ST;        // 96 KB
constexpr int AV_DSMEM = 2 * AV_STG + 1024;

__global__ __launch_bounds__(544)
void av16_kernel(const __grid_constant__ CUtensorMap tma_v,
                 const __grid_constant__ CUtensorMap tma_e,
                 const float* __restrict__ x,
                 const float* __restrict__ rs,
                 const float* __restrict__ gamma,
                 float* __restrict__ outp)
{
    __shared__ __align__(8) uint64_t s_bar[4];
    extern __shared__ char dsm[];
    const uint32_t dbase = (smem_to_u32(dsm) + 1023) & ~1023u;
    const uint32_t sbar  = smem_to_u32(s_bar);

    const int tid = threadIdx.x, wid = tid >> 5, lid = tid & 31;
    const int mBase = blockIdx.x * 256;     // c
    const int nBase = blockIdx.y * 128;     // i
    const int b     = blockIdx.z;
    const int nchunk = NN / 128;            // 32

    if (tid == 0) {
        #pragma unroll
        for (int s = 0; s < 2; s++) {
            MBARRIER_INIT(sbar + s * 16, 1);
            MBARRIER_INIT(sbar + s * 16 + 8, 16);
        }
    }
    __syncthreads();

    if (tid == 512) {
        int ph = 1, st = 0;
        for (int c = 0; c < nchunk; c++) {
            MBARRIER_WAIT_PARITY(sbar + st * 16 + 8, ph);
            MBARRIER_EXPECT_TX(sbar + st * 16, AV_STG);
            const uint32_t SB = dbase + st * AV_STG;
            TMA_LOAD_3D(SB,                 &tma_v, c * 128,      mBase, b, sbar + st * 16);
            TMA_LOAD_3D(SB + 32768,         &tma_v, c * 128 + 64, mBase, b, sbar + st * 16);
            TMA_LOAD_3D(SB + AV_A_ST,         &tma_e, c * 128,      nBase, b, sbar + st * 16);
            TMA_LOAD_3D(SB + AV_A_ST + 16384, &tma_e, c * 128 + 64, nBase, b, sbar + st * 16);
            if (++st == 2) { st = 0; ph ^= 1; }
        }
    }

    if (wid < 16) {
        const int wm = wid & 3, wn = wid >> 2;
        const int mWarp = wm * 64, nWarp = wn * 32;
        const int laneA = lid & 15;
        const int hAu   = (lid >> 4) & 1;
        const int laneB = (lid & 7) + ((lid & 16) ? 8 : 0);
        const int hBu   = (lid >> 3) & 1;
        const int xor7  = lid & 7;

        float cacc[4][4][4] = {};

        int ph = 0, st = 0;
        for (int c = 0; c < nchunk; c++) {
            MBARRIER_WAIT_PARITY(sbar + st * 16, ph);
            const uint32_t Ab = dbase + st * AV_STG;
            const uint32_t Bb = Ab + AV_A_ST;
            const uint32_t aRowAddr = Ab + (mWarp + laneA) * 128;
            const uint32_t bRowAddr = Bb + (nWarp + laneB) * 128;

            #pragma unroll
            for (int kt = 0; kt < 2; kt++) {
                #pragma unroll
                for (int ks = 0; ks < 4; ks++) {
                    uint32_t af[4][4];
                    uint32_t bf[4][2];
                    const uint32_t cA = (uint32_t)(((2 * ks + hAu) ^ xor7) << 4);
                    const uint32_t cB = (uint32_t)(((2 * ks + hBu) ^ xor7) << 4);
                    #pragma unroll
                    for (int mt = 0; mt < 4; mt++)
                        LDSM_X4(af[mt][0], af[mt][1], af[mt][2], af[mt][3],
                                aRowAddr + kt * 32768 + mt * (16 * 128) + cA);
                    #pragma unroll
                    for (int p = 0; p < 2; p++) {
                        uint32_t r0, r1, r2, r3;
                        LDSM_X4(r0, r1, r2, r3, bRowAddr + kt * 16384 + p * (16 * 128) + cB);
                        bf[2*p][0] = r0; bf[2*p][1] = r1;
                        bf[2*p+1][0] = r2; bf[2*p+1][1] = r3;
                    }
                    #pragma unroll
                    for (int mt = 0; mt < 4; mt++)
                        #pragma unroll
                        for (int nt = 0; nt < 4; nt++)
                            mma_f16(cacc[mt][nt], af[mt], bf[nt]);
                }
            }
            if (lid == 0) MBARRIER_ARRIVE(sbar + st * 16 + 8);
            if (++st == 2) { st = 0; ph ^= 1; }
        }

        const int g = lid >> 2, t4 = lid & 3;
        const float gm = gamma[0];
        const float* rs_b = rs + (size_t)b * NN;
        const float* xb = x + (size_t)b * CC * NN;
        float* ob = outp + (size_t)b * CC * NN;

        #pragma unroll
        for (int mt = 0; mt < 4; mt++) {
            const int r0 = mBase + mWarp + mt * 16 + g;
            const int r1 = r0 + 8;
            #pragma unroll
            for (int nt = 0; nt < 4; nt++) {
                const int col = nBase + nWarp + nt * 8 + t4 * 2;
                const float i0 = __fdividef(1.0f, rs_b[col]);
                const float i1 = __fdividef(1.0f, rs_b[col + 1]);
                const float2 x0 = *(const float2*)&xb[(size_t)r0 * NN + col];
                const float2 x1 = *(const float2*)&xb[(size_t)r1 * NN + col];
                *(float2*)&ob[(size_t)r0 * NN + col] =
                    make_float2(gm * cacc[mt][nt][0] * i0 + x0.x,
                                gm * cacc[mt][nt][1] * i1 + x0.y);
                *(float2*)&ob[(size_t)r1 * NN + col] =
                    make_float2(gm * cacc[mt][nt][2] * i0 + x1.x,
                                gm * cacc[mt][nt][3] * i1 + x1.y);
            }
        }
    }
}

// ---------------------------------------------------------------------------
// Host side
// ---------------------------------------------------------------------------
typedef CUresult (*EncodeFn)(CUtensorMap*, CUtensorMapDataType, cuuint32_t, void*,
                             const cuuint64_t*, const cuuint64_t*, const cuuint32_t*,
                             const cuuint32_t*, CUtensorMapInterleave, CUtensorMapSwizzle,
                             CUtensorMapL2promotion, CUtensorMapFloatOOBfill);

static void build_tm(EncodeFn enc, CUtensorMap* tm, void* ptr,
                     uint64_t d0, uint64_t d1, uint64_t d2,
                     uint64_t s1b, uint64_t s2b, uint32_t b0, uint32_t b1)
{
    cuuint64_t dims[3] = {d0, d1, d2};
    cuuint64_t str[2]  = {s1b, s2b};
    cuuint32_t box[3]  = {b0, b1, 1};
    cuuint32_t es[3]   = {1, 1, 1};
    enc(tm, CU_TENSOR_MAP_DATA_TYPE_FLOAT16, 3, ptr, dims, str, box, es,
        CU_TENSOR_MAP_INTERLEAVE_NONE, CU_TENSOR_MAP_SWIZZLE_128B,
        CU_TENSOR_MAP_L2_PROMOTION_L2_128B, CU_TENSOR_MAP_FLOAT_OOB_FILL_NONE);
}

extern "C" void kernel_launch(void* const* d_in, const int* in_sizes, int n_in,
                              void* d_out, int out_size)
{
    (void)in_sizes; (void)n_in; (void)out_size;
    const float* x     = (const float*)d_in[0];
    const float* Wq    = (const float*)d_in[1];
    const float* bq    = (const float*)d_in[2];
    const float* Wk    = (const float*)d_in[3];
    const float* bk    = (const float*)d_in[4];
    const float* Wv    = (const float*)d_in[5];
    const float* bv    = (const float*)d_in[6];
    const float* gamma = (const float*)d_in[7];
    float* out = (float*)d_out;

    EncodeFn enc = nullptr;
    cudaDriverEntryPointQueryResult qr;
    cudaGetDriverEntryPointByVersion("cuTensorMapEncodeTiled", (void**)&enc, 12000,
                                     cudaEnableDefault, &qr);

    void *pqk, *pvh, *peh, *pxT, *pwr, *pwqk, *pbqk, *prs, *prm;
    cudaGetSymbolAddress(&pqk,  g_qkh);
    cudaGetSymbolAddress(&pvh,  g_vh);
    cudaGetSymbolAddress(&peh,  g_eh);
    cudaGetSymbolAddress(&pxT,  g_xTh);
    cudaGetSymbolAddress(&pwr,  g_wrh);
    cudaGetSymbolAddress(&pwqk, g_wqkh);
    cudaGetSymbolAddress(&pbqk, g_bqk);
    cudaGetSymbolAddress(&prs,  g_rs);
    cudaGetSymbolAddress(&prm,  g_rm);

    CUtensorMap tmXT_A64, tmXT_B, tmWQK, tmWV, tmQKa, tmQKb, tmVh256, tmEh128;
    // xT as A for qk-proj (box 64 rows, MT=1) and as B for v-proj (box 128)
    build_tm(enc, &tmXT_A64, pxT, CC, NN, BB, (uint64_t)CC * 2, (uint64_t)NN * CC * 2, 64, 64);
    build_tm(enc, &tmXT_B,   pxT, CC, NN, BB, (uint64_t)CC * 2, (uint64_t)NN * CC * 2, 64, 128);
    build_tm(enc, &tmWQK, pwqk, CC, QK, 1, (uint64_t)CC * 2, (uint64_t)QK * CC * 2, 64, 128);
    build_tm(enc, &tmWV,  pwr,  CC, CC, 1, (uint64_t)CC * 2, (uint64_t)CC * CC * 2, 64, 256);
    build_tm(enc, &tmQKa, pqk, QK, NN, BB, (uint64_t)QK * 2, (uint64_t)NN * QK * 2, 64, 256);
    build_tm(enc, &tmQKb, pqk, QK, NN, BB, (uint64_t)QK * 2, (uint64_t)NN * QK * 2, 64, 128);
    build_tm(enc, &tmVh256, pvh, NN, CC, BB, (uint64_t)NN * 2, (uint64_t)CC * NN * 2, 64, 256);
    build_tm(enc, &tmEh128, peh, NN, NN, BB, (uint64_t)NN * 2, (uint64_t)NN * NN * 2, 64, 128);

    constexpr int DS1 = NSTAGE * (64 * 128 + B16_BY) + 1024;    // MT=1
    constexpr int DS4 = NSTAGE * (256 * 128 + B16_BY) + 1024;   // MT=4
    cudaFuncSetAttribute(gemm16_kernel<1>, cudaFuncAttributeMaxDynamicSharedMemorySize, DS1);
    cudaFuncSetAttribute(gemm16_kernel<4>, cudaFuncAttributeMaxDynamicSharedMemorySize, DS4);
    cudaFuncSetAttribute(av16_kernel, cudaFuncAttributeMaxDynamicSharedMemorySize, AV_DSMEM);

    float* frs = (float*)prs;
    unsigned* frm = (unsigned*)prm;

    // 1. prep
    xT_half_kernel<<<dim3(NN / 32, CC / 32, BB), 256>>>(x);
    w_half_kernel<<<(CC * CC) / 256, 256>>>(Wv);
    wqk_prep_kernel<<<(QK * CC) / 256, 256>>>(Wq, bq, Wk, bk);
    // 2. qk projection (MT=1, BM=64): 128 CTAs, K=512
    gemm16_kernel<1><<<dim3(QK / BN, NN / 64, BB), 544, DS1>>>(
        tmXT_A64, tmWQK, CC, 3, 1, 0, 0, 0, (const float*)pbqk, frs, frm,
        pqk, (size_t)NN * QK, QK);
    // 3. v projection (MT=4): g_vh[c][n] = wr·xT^T + bv[c], K=512
    gemm16_kernel<4><<<dim3(NN / BN, CC / 256, BB), 544, DS4>>>(
        tmWV, tmXT_B, CC, 0, 0, 1, 0, 0, bv, frs, frm,
        pvh, (size_t)CC * NN, NN);
    // 4. row max pass (MT=4): rm[i] = max_j q_i·k_j, K=64
    gemm16_kernel<4><<<dim3(NN / BN, NN / 256, BB), 544, DS4>>>(
        tmQKa, tmQKb, DD, 4, 1, 1, 0, DD, nullptr, frs, frm,
        nullptr, 0, 0);
    // 5. scores (MT=4): g_eh[i][j] = fp16(exp(q·k - rm[i])), rowsums fp32
    gemm16_kernel<4><<<dim3(NN / BN, NN / 256, BB), 544, DS4>>>(
        tmQKa, tmQKb, DD, 2, 1, 1, 0, DD, nullptr, frs, frm,
        peh, (size_t)NN * NN, NN);
    // 6. AV (fp16, BK=128): out = gamma*(v·e^T)/rs + x, K=4096
    av16_kernel<<<dim3(CC / 256, NN / 128, BB), 544, AV_DSMEM>>>(
        tmVh256, tmEh128, x, frs, gamma, out);
}